// round 1
// baseline (speedup 1.0000x reference)
#include <cuda_runtime.h>

// Problem constants
#define B_ 4
#define T_ 2048
#define C_ 1024
#define H_ 16
#define D_ 64
#define BT_ (B_ * T_)            // 8192

// Scratch (device globals — no allocation allowed)
__device__ float g_q[(size_t)B_ * H_ * T_ * D_];   // Q in [B,H,T,D], pre-scaled by 1/sqrt(D)
__device__ float g_att[(size_t)BT_ * C_];          // attention output in [B,T,C]

// ---------------------------------------------------------------------------
// GEMM: [M=8192, K=1024] x [K=1024, N] + bias, 128x128 tile, 8x8 per thread.
// MODE 0: A = x (arg), scatter q->g_q (scaled 0.125), k->o1, v->o2 in [B,H,T,D]
// MODE 1: A = g_att (device global), plain output o0[row*N+col]
// ---------------------------------------------------------------------------
template <int N, int MODE>
__global__ __launch_bounds__(256, 2)
void gemm1024_kernel(const float* __restrict__ A,
                     const float* __restrict__ W,
                     const float* __restrict__ bias,
                     float* __restrict__ o0,
                     float* __restrict__ o1,
                     float* __restrict__ o2)
{
    constexpr int K = 1024;
    __shared__ float As[8][128];   // transposed: As[k][m]
    __shared__ float Bs[8][128];   // Bs[k][n]

    const int tid = threadIdx.x;
    const int tx = tid & 15;       // 0..15 -> n
    const int ty = tid >> 4;       // 0..15 -> m
    const int n0 = blockIdx.x * 128;
    const int m0 = blockIdx.y * 128;

    const float* Ap = (MODE == 0) ? A : g_att;

    float acc[8][8];
#pragma unroll
    for (int i = 0; i < 8; i++)
#pragma unroll
        for (int j = 0; j < 8; j++) acc[i][j] = 0.f;

    // loaders
    const int arow = tid >> 1;          // 0..127
    const int acol = (tid & 1) << 2;    // 0 or 4
    const int brow = tid >> 5;          // 0..7
    const int bcol = (tid & 31) << 2;   // 0..124

    const float* Ag = Ap + (size_t)(m0 + arow) * K + acol;
    const float* Wg = W + (size_t)brow * N + n0 + bcol;

    for (int kk = 0; kk < K; kk += 8) {
        float4 a4 = *(const float4*)(Ag + kk);
        float4 b4 = *(const float4*)(Wg + (size_t)kk * N);
        As[acol + 0][arow] = a4.x;
        As[acol + 1][arow] = a4.y;
        As[acol + 2][arow] = a4.z;
        As[acol + 3][arow] = a4.w;
        *(float4*)&Bs[brow][bcol] = b4;
        __syncthreads();
#pragma unroll
        for (int k = 0; k < 8; k++) {
            float ar[8], br[8];
            *(float4*)(ar)     = *(const float4*)&As[k][ty * 8];
            *(float4*)(ar + 4) = *(const float4*)&As[k][ty * 8 + 4];
            *(float4*)(br)     = *(const float4*)&Bs[k][tx * 8];
            *(float4*)(br + 4) = *(const float4*)&Bs[k][tx * 8 + 4];
#pragma unroll
            for (int i = 0; i < 8; i++)
#pragma unroll
                for (int j = 0; j < 8; j++)
                    acc[i][j] += ar[i] * br[j];
        }
        __syncthreads();
    }

    if (MODE == 0) {
        // N=3072; 128-wide tile lies fully inside one of {q,k,v} (1024-aligned)
        const int seg = n0 >> 10;
#pragma unroll
        for (int i = 0; i < 8; i++) {
            const int row = m0 + ty * 8 + i;
            const int b = row >> 11;          // T_=2048
            const int t = row & (T_ - 1);
#pragma unroll
            for (int j = 0; j < 8; j++) {
                const int col = n0 + tx * 8 + j;
                const int c0 = col - (seg << 10);
                const int h = c0 >> 6;
                const int d = c0 & 63;
                const size_t idx = ((size_t)(b * H_ + h) * T_ + t) * D_ + d;
                const float v = acc[i][j] + bias[col];
                if (seg == 0)      g_q[idx] = v * 0.125f;   // fold 1/sqrt(64)
                else if (seg == 1) o1[idx] = v;
                else               o2[idx] = v;
            }
        }
    } else {
#pragma unroll
        for (int i = 0; i < 8; i++) {
            const int row = m0 + ty * 8 + i;
#pragma unroll
            for (int j = 0; j < 8; j++) {
                const int col = n0 + tx * 8 + j;
                o0[(size_t)row * N + col] = acc[i][j] + bias[col];
            }
        }
    }
}

// ---------------------------------------------------------------------------
// Flash attention, fp32 SIMT. One block = one (b,h) x one 64-row q-block.
// Causal: only iterate kv tiles kb <= qb; mask inside the diagonal tile.
// Threads 256 as 16x16; thread owns S/P 4x4 and O 4x4.
// ---------------------------------------------------------------------------
__device__ __forceinline__ float redmax16(float v) {
    v = fmaxf(v, __shfl_xor_sync(0xffffffffu, v, 1));
    v = fmaxf(v, __shfl_xor_sync(0xffffffffu, v, 2));
    v = fmaxf(v, __shfl_xor_sync(0xffffffffu, v, 4));
    v = fmaxf(v, __shfl_xor_sync(0xffffffffu, v, 8));
    return v;
}
__device__ __forceinline__ float redsum16(float v) {
    v += __shfl_xor_sync(0xffffffffu, v, 1);
    v += __shfl_xor_sync(0xffffffffu, v, 2);
    v += __shfl_xor_sync(0xffffffffu, v, 4);
    v += __shfl_xor_sync(0xffffffffu, v, 8);
    return v;
}

__global__ __launch_bounds__(256, 2)
void attn_kernel(const float* __restrict__ Kg, const float* __restrict__ Vg)
{
    __shared__ float Qs[64][64];   // [i][d]
    __shared__ float KP[64][64];   // K^T as [d][j], then reused for P as [i][j]
    __shared__ float Vs[64][64];   // [j][d]
    // total static smem = 49152 B (exactly 48KB)

    const int tid = threadIdx.x;
    const int tx = tid & 15;
    const int ty = tid >> 4;
    const int qb = blockIdx.x;     // 0..31
    const int bh = blockIdx.y;     // 0..63

    const float* Qp = g_q + (size_t)bh * T_ * D_ + (size_t)qb * 64 * D_;
    const float* Kp = Kg + (size_t)bh * T_ * D_;
    const float* Vp = Vg + (size_t)bh * T_ * D_;

    const int lr = tid >> 2;          // 0..63 (loader row)
    const int lc = (tid & 3) << 4;    // 0,16,32,48 (loader col base)

#pragma unroll
    for (int q = 0; q < 4; q++)
        *(float4*)&Qs[lr][lc + q * 4] = *(const float4*)(Qp + lr * D_ + lc + q * 4);

    const int i0 = ty * 4;
    const int j0 = tx * 4;
    const int d0 = tx * 4;

    float m_i[4], l_i[4], Oa[4][4];
#pragma unroll
    for (int ii = 0; ii < 4; ii++) {
        m_i[ii] = -1e30f;
        l_i[ii] = 0.f;
#pragma unroll
        for (int dd = 0; dd < 4; dd++) Oa[ii][dd] = 0.f;
    }

    for (int kb = 0; kb <= qb; kb++) {
        __syncthreads();   // prior-iter smem reads done (also covers Qs load at kb=0)
        {
            const float* kr = Kp + (size_t)(kb * 64 + lr) * D_ + lc;
            const float* vr = Vp + (size_t)(kb * 64 + lr) * D_ + lc;
#pragma unroll
            for (int q = 0; q < 4; q++) {
                float4 k4 = *(const float4*)(kr + q * 4);
                KP[lc + q * 4 + 0][lr] = k4.x;
                KP[lc + q * 4 + 1][lr] = k4.y;
                KP[lc + q * 4 + 2][lr] = k4.z;
                KP[lc + q * 4 + 3][lr] = k4.w;
                *(float4*)&Vs[lr][lc + q * 4] = *(const float4*)(vr + q * 4);
            }
        }
        __syncthreads();

        // S = Q K^T (Q pre-scaled)
        float S[4][4];
#pragma unroll
        for (int ii = 0; ii < 4; ii++)
#pragma unroll
            for (int jj = 0; jj < 4; jj++) S[ii][jj] = 0.f;

#pragma unroll
        for (int d = 0; d < 64; d += 4) {
            float qv[4][4], kv[4][4];
#pragma unroll
            for (int ii = 0; ii < 4; ii++)
                *(float4*)qv[ii] = *(const float4*)&Qs[i0 + ii][d];
#pragma unroll
            for (int dc = 0; dc < 4; dc++)
                *(float4*)kv[dc] = *(const float4*)&KP[d + dc][j0];
#pragma unroll
            for (int ii = 0; ii < 4; ii++)
#pragma unroll
                for (int jj = 0; jj < 4; jj++)
                    S[ii][jj] += qv[ii][0] * kv[0][jj] + qv[ii][1] * kv[1][jj]
                               + qv[ii][2] * kv[2][jj] + qv[ii][3] * kv[3][jj];
        }

        if (kb == qb) {
#pragma unroll
            for (int ii = 0; ii < 4; ii++)
#pragma unroll
                for (int jj = 0; jj < 4; jj++)
                    if (j0 + jj > i0 + ii) S[ii][jj] = -1e30f;
        }

        // online softmax (state replicated across the 16 row-mate lanes)
        float alpha[4], rsum[4];
#pragma unroll
        for (int ii = 0; ii < 4; ii++) {
            float rmax = fmaxf(fmaxf(S[ii][0], S[ii][1]), fmaxf(S[ii][2], S[ii][3]));
            rmax = redmax16(rmax);
            const float mnew = fmaxf(m_i[ii], rmax);
            alpha[ii] = __expf(m_i[ii] - mnew);
            m_i[ii] = mnew;
            float s = 0.f;
#pragma unroll
            for (int jj = 0; jj < 4; jj++) {
                const float p = __expf(S[ii][jj] - mnew);
                S[ii][jj] = p;
                s += p;
            }
            rsum[ii] = redsum16(s);
        }
#pragma unroll
        for (int ii = 0; ii < 4; ii++) {
            l_i[ii] = l_i[ii] * alpha[ii] + rsum[ii];
#pragma unroll
            for (int dd = 0; dd < 4; dd++) Oa[ii][dd] *= alpha[ii];
        }

        __syncthreads();   // everyone done reading KP (as K^T)
#pragma unroll
        for (int ii = 0; ii < 4; ii++)
#pragma unroll
            for (int jj = 0; jj < 4; jj++)
                KP[i0 + ii][j0 + jj] = S[ii][jj];   // KP now holds P
        __syncthreads();

        // O += P @ V
#pragma unroll
        for (int j = 0; j < 64; j += 4) {
            float pv[4][4], vv[4][4];
#pragma unroll
            for (int ii = 0; ii < 4; ii++)
                *(float4*)pv[ii] = *(const float4*)&KP[i0 + ii][j];
#pragma unroll
            for (int jc = 0; jc < 4; jc++)
                *(float4*)vv[jc] = *(const float4*)&Vs[j + jc][d0];
#pragma unroll
            for (int ii = 0; ii < 4; ii++)
#pragma unroll
                for (int dd = 0; dd < 4; dd++)
                    Oa[ii][dd] += pv[ii][0] * vv[0][dd] + pv[ii][1] * vv[1][dd]
                                + pv[ii][2] * vv[2][dd] + pv[ii][3] * vv[3][dd];
        }
    }

    // write O / l  into [B,T,C] layout for the proj GEMM
    const int b = bh >> 4;
    const int h = bh & 15;
#pragma unroll
    for (int ii = 0; ii < 4; ii++) {
        const float inv = 1.f / l_i[ii];
        const int t = qb * 64 + i0 + ii;
        float4 o4;
        o4.x = Oa[ii][0] * inv;
        o4.y = Oa[ii][1] * inv;
        o4.z = Oa[ii][2] * inv;
        o4.w = Oa[ii][3] * inv;
        *(float4*)&g_att[((size_t)(b * T_ + t)) * C_ + h * 64 + d0] = o4;
    }
}

// ---------------------------------------------------------------------------
// Launch. Inputs (metadata order): x, mask, W_attn, b_attn, W_proj, b_proj.
// Output: [out (B,T,C) | k (B,H,T,D) | v (B,H,T,D)] fp32, concatenated.
// mask is exactly causal triu(NEG): implemented directly (tile skipping).
// ---------------------------------------------------------------------------
extern "C" void kernel_launch(void* const* d_in, const int* in_sizes, int n_in,
                              void* d_out, int out_size)
{
    (void)in_sizes; (void)n_in; (void)out_size;
    const float* x      = (const float*)d_in[0];
    const float* W_attn = (const float*)d_in[2];
    const float* b_attn = (const float*)d_in[3];
    const float* W_proj = (const float*)d_in[4];
    const float* b_proj = (const float*)d_in[5];

    float* out  = (float*)d_out;
    float* kout = out + (size_t)B_ * H_ * T_ * D_;      // +8388608
    float* vout = kout + (size_t)B_ * H_ * T_ * D_;     // +16777216

    // 1) QKV GEMM + bias + scatter (q scaled into g_q; k,v straight to output)
    gemm1024_kernel<3 * C_, 0><<<dim3(24, 64), 256>>>(x, W_attn, b_attn,
                                                      nullptr, kout, vout);
    // 2) causal flash attention -> g_att in [B,T,C]
    attn_kernel<<<dim3(T_ / 64, B_ * H_), 256>>>(kout, vout);
    // 3) output projection + bias -> d_out[0..B*T*C)
    gemm1024_kernel<C_, 1><<<dim3(8, 64), 256>>>(nullptr, W_proj, b_proj,
                                                 out, nullptr, nullptr);
}

// round 3
// speedup vs baseline: 1.6866x; 1.6866x over previous
#include <cuda_runtime.h>
#include <cuda_bf16.h>
#include <cstdint>

// Problem constants
#define B_ 4
#define T_ 2048
#define C_ 1024
#define H_ 16
#define D_ 64
#define BT_ (B_ * T_)            // 8192
#define KDIM 1024

// ---------------------------------------------------------------------------
// Scratch (device globals — no allocation allowed)
// ---------------------------------------------------------------------------
__device__ float g_q[(size_t)BT_ * C_];            // Q fp32 [B,H,T,D], pre-scaled
__device__ float g_att[(size_t)BT_ * C_];          // attention out fp32 [B,T,C]
__device__ __nv_bfloat16 g_xh[(size_t)BT_ * KDIM]; // x hi/lo
__device__ __nv_bfloat16 g_xl[(size_t)BT_ * KDIM];
__device__ __nv_bfloat16 g_wh[(size_t)3 * C_ * KDIM]; // W_attn^T hi/lo [N=3072][K=1024]
__device__ __nv_bfloat16 g_wl[(size_t)3 * C_ * KDIM];
__device__ __nv_bfloat16 g_ph[(size_t)C_ * KDIM];     // W_proj^T hi/lo [N=1024][K=1024]
__device__ __nv_bfloat16 g_pl[(size_t)C_ * KDIM];
__device__ __nv_bfloat16 g_ah[(size_t)BT_ * KDIM];    // attn-out hi/lo
__device__ __nv_bfloat16 g_al[(size_t)BT_ * KDIM];

// ---------------------------------------------------------------------------
// mma.sync / ldmatrix helpers (sm_80-era PTX — legal at compute_103 base)
// ---------------------------------------------------------------------------
__device__ __forceinline__ uint32_t s2u(const void* p) {
    uint32_t a;
    asm("{ .reg .u64 t; cvta.to.shared.u64 t, %1; cvt.u32.u64 %0, t; }" : "=r"(a) : "l"(p));
    return a;
}
__device__ __forceinline__ uint32_t swz(uint32_t off) {   // SW128
    return off ^ ((off >> 3) & 0x70);
}
__device__ __forceinline__ void ldsm4(uint32_t* r, uint32_t addr) {
    asm volatile("ldmatrix.sync.aligned.m8n8.x4.shared.b16 {%0,%1,%2,%3}, [%4];"
                 : "=r"(r[0]), "=r"(r[1]), "=r"(r[2]), "=r"(r[3]) : "r"(addr));
}
__device__ __forceinline__ void mma16816(float* c, const uint32_t* a, const uint32_t* b) {
    asm volatile(
        "mma.sync.aligned.m16n8k16.row.col.f32.bf16.bf16.f32 "
        "{%0,%1,%2,%3}, {%4,%5,%6,%7}, {%8,%9}, {%0,%1,%2,%3};"
        : "+f"(c[0]), "+f"(c[1]), "+f"(c[2]), "+f"(c[3])
        : "r"(a[0]), "r"(a[1]), "r"(a[2]), "r"(a[3]), "r"(b[0]), "r"(b[1]));
}

// ---------------------------------------------------------------------------
// Conversion kernels
// ---------------------------------------------------------------------------
template <int SRCMODE>
__global__ void split_kernel(const float* __restrict__ xin)
{
    const float* s = (SRCMODE == 0) ? xin : g_att;
    __nv_bfloat16* h = (SRCMODE == 0) ? g_xh : g_ah;
    __nv_bfloat16* l = (SRCMODE == 0) ? g_xl : g_al;
    const size_t n4 = (size_t)BT_ * KDIM / 4;
    for (size_t i = (size_t)blockIdx.x * blockDim.x + threadIdx.x; i < n4;
         i += (size_t)gridDim.x * blockDim.x) {
        float4 v = ((const float4*)s)[i];
        __nv_bfloat162 h01, h23, l01, l23;
        h01.x = __float2bfloat16(v.x); h01.y = __float2bfloat16(v.y);
        h23.x = __float2bfloat16(v.z); h23.y = __float2bfloat16(v.w);
        l01.x = __float2bfloat16(v.x - __bfloat162float(h01.x));
        l01.y = __float2bfloat16(v.y - __bfloat162float(h01.y));
        l23.x = __float2bfloat16(v.z - __bfloat162float(h23.x));
        l23.y = __float2bfloat16(v.w - __bfloat162float(h23.y));
        ((__nv_bfloat162*)h)[2 * i]     = h01;
        ((__nv_bfloat162*)h)[2 * i + 1] = h23;
        ((__nv_bfloat162*)l)[2 * i]     = l01;
        ((__nv_bfloat162*)l)[2 * i + 1] = l23;
    }
}

// fp32 W [K=1024, NC] row-major -> transposed hi/lo bf16 [NC, 1024]
template <int W>
__global__ void tsplit_kernel(const float* __restrict__ src)
{
    constexpr int NC = (W == 0) ? 3 * C_ : C_;
    __nv_bfloat16* dh = (W == 0) ? g_wh : g_ph;
    __nv_bfloat16* dl = (W == 0) ? g_wl : g_pl;
    __shared__ float tile[32][33];
    const int x = blockIdx.x * 32 + threadIdx.x;
    const int y0 = blockIdx.y * 32;
#pragma unroll
    for (int j = 0; j < 32; j += 8)
        tile[threadIdx.y + j][threadIdx.x] = src[(size_t)(y0 + threadIdx.y + j) * NC + x];
    __syncthreads();
    const int ox = y0 + threadIdx.x;
    const int oyb = blockIdx.x * 32;
#pragma unroll
    for (int j = 0; j < 32; j += 8) {
        float v = tile[threadIdx.x][threadIdx.y + j];
        __nv_bfloat16 hh = __float2bfloat16(v);
        dh[(size_t)(oyb + threadIdx.y + j) * KDIM + ox] = hh;
        dl[(size_t)(oyb + threadIdx.y + j) * KDIM + ox] =
            __float2bfloat16(v - __bfloat162float(hh));
    }
}

// ---------------------------------------------------------------------------
// bf16x3 GEMM via mma.sync: D[M=8192,N] = A[M,1024] x B[N,1024]^T.
// CTA tile 128x128, K_chunk=64, 3-stage cp.async pipeline, 8 warps (64x32 each).
// Stage layout: [Ah 16KB][Al 16KB][Bh 16KB][Bl 16KB]; each tile 128 rows x 128B, SW128.
// MODE 0: scatter q(g_q,*0.125)/k(o1)/v(o2)   MODE 1: plain o0
// ---------------------------------------------------------------------------
#define SM_STAGE 65536
#define SMEM_GEMM_BYTES 196608   // 3 stages

template <int MODE>
__global__ __launch_bounds__(256, 1)
void mma_gemm(const float* __restrict__ bias,
              float* __restrict__ o0, float* __restrict__ o1, float* __restrict__ o2)
{
    extern __shared__ __align__(1024) char smem[];
    const uint32_t sm = s2u(smem);
    const int tid = threadIdx.x;
    const int wid = tid >> 5;
    const int lid = tid & 31;
    const int n0 = blockIdx.x * 128;
    const int m0 = blockIdx.y * 128;

    const __nv_bfloat16* Ahp = (MODE == 0) ? g_xh : g_ah;
    const __nv_bfloat16* Alp = (MODE == 0) ? g_xl : g_al;
    const __nv_bfloat16* Bhp = (MODE == 0) ? g_wh : g_ph;
    const __nv_bfloat16* Blp = (MODE == 0) ? g_wl : g_pl;

    // ---- cp.async copy plan: 4096 x 16B per stage, 16 per thread ----
    const __nv_bfloat16* srcs[16];
    uint32_t dsts[16];
#pragma unroll
    for (int r = 0; r < 16; r++) {
        const int id = tid + r * 256;
        const int bsel = id >> 10;           // 0:Ah 1:Al 2:Bh 3:Bl
        const int row = (id >> 3) & 127;
        const int c16 = id & 7;
        dsts[r] = (uint32_t)(bsel * 16384) + swz((uint32_t)(row * 128 + c16 * 16));
        const __nv_bfloat16* base;
        if (bsel == 0)      base = Ahp + (size_t)(m0 + row) * KDIM;
        else if (bsel == 1) base = Alp + (size_t)(m0 + row) * KDIM;
        else if (bsel == 2) base = Bhp + (size_t)(n0 + row) * KDIM;
        else                base = Blp + (size_t)(n0 + row) * KDIM;
        srcs[r] = base + c16 * 8;
    }
    auto issue_loads = [&](int c, int s) {
        const uint32_t sb = sm + (uint32_t)s * SM_STAGE;
#pragma unroll
        for (int r = 0; r < 16; r++)
            asm volatile("cp.async.cg.shared.global [%0], [%1], 16;"
                         :: "r"(sb + dsts[r]), "l"(srcs[r] + c * 64) : "memory");
        asm volatile("cp.async.commit_group;" ::: "memory");
    };

    // ---- warp tiling ----
    const int warpM = (wid & 1) * 64;        // 0 or 64
    const int warpN = (wid >> 1) * 32;       // 0,32,64,96
    const int g = lid >> 2;                  // groupID
    const int tig = lid & 3;
    const int aRow = lid & 15;               // ldmatrix A lane row
    const int aKb = (lid >> 4) * 16;         // ldmatrix A lane k-byte
    const int bRow = ((lid >> 4) & 1) * 8 + (lid & 7);   // ldmatrix B lane n-row
    const int bKb = ((lid >> 3) & 1) * 16;               // ldmatrix B lane k-byte

    float Cr[4][4][4];
#pragma unroll
    for (int mi = 0; mi < 4; mi++)
#pragma unroll
        for (int j = 0; j < 4; j++)
#pragma unroll
            for (int q = 0; q < 4; q++) Cr[mi][j][q] = 0.f;

    issue_loads(0, 0);
    issue_loads(1, 1);

    for (int c = 0; c < 16; c++) {
        const int s = c % 3;
        if (c < 15) asm volatile("cp.async.wait_group 1;" ::: "memory");
        else        asm volatile("cp.async.wait_group 0;" ::: "memory");
        __syncthreads();

        const uint32_t sb = sm + (uint32_t)s * SM_STAGE;
        const uint32_t tAh = sb, tAl = sb + 16384, tBh = sb + 32768, tBl = sb + 49152;

#pragma unroll
        for (int ks = 0; ks < 4; ks++) {
            const int kb = ks * 32;
            uint32_t ah[4][4], al[4][4], bh[2][4], bl[2][4];
#pragma unroll
            for (int mi = 0; mi < 4; mi++) {
                const uint32_t off = swz((uint32_t)((warpM + mi * 16 + aRow) * 128 + kb + aKb));
                ldsm4(ah[mi], tAh + off);
                ldsm4(al[mi], tAl + off);
            }
#pragma unroll
            for (int jp = 0; jp < 2; jp++) {
                const uint32_t off = swz((uint32_t)((warpN + jp * 16 + bRow) * 128 + kb + bKb));
                ldsm4(bh[jp], tBh + off);
                ldsm4(bl[jp], tBl + off);
            }
#pragma unroll
            for (int mi = 0; mi < 4; mi++)
#pragma unroll
                for (int j = 0; j < 4; j++) {
                    const int jp = j >> 1, o = (j & 1) * 2;
                    mma16816(Cr[mi][j], ah[mi], &bh[jp][o]);
                    mma16816(Cr[mi][j], ah[mi], &bl[jp][o]);
                    mma16816(Cr[mi][j], al[mi], &bh[jp][o]);
                }
        }
        __syncthreads();
        if (c + 2 < 16) issue_loads(c + 2, (c + 2) % 3);
    }

    // ---- epilogue ----
#pragma unroll
    for (int mi = 0; mi < 4; mi++)
#pragma unroll
        for (int j = 0; j < 4; j++) {
            const int col = n0 + warpN + j * 8 + tig * 2;
            const float2 bb = *(const float2*)(bias + col);
#pragma unroll
            for (int half = 0; half < 2; half++) {
                const int row = m0 + warpM + mi * 16 + g + half * 8;
                float2 v;
                v.x = Cr[mi][j][half * 2 + 0] + bb.x;
                v.y = Cr[mi][j][half * 2 + 1] + bb.y;
                if (MODE == 0) {
                    const int seg = col >> 10;
                    const int c0 = col & 1023;
                    const int h = c0 >> 6;
                    const int dd = c0 & 63;
                    const int b = row >> 11;
                    const int t = row & (T_ - 1);
                    const size_t idx = ((size_t)(b * H_ + h) * T_ + t) * D_ + dd;
                    if (seg == 0) {
                        v.x *= 0.125f; v.y *= 0.125f;
                        *(float2*)&g_q[idx] = v;
                    } else if (seg == 1) {
                        *(float2*)&o1[idx] = v;
                    } else {
                        *(float2*)&o2[idx] = v;
                    }
                } else {
                    *(float2*)&o0[(size_t)row * C_ + col] = v;
                }
            }
        }
}

// ---------------------------------------------------------------------------
// Flash attention, fp32 SIMT (unchanged).
// ---------------------------------------------------------------------------
__device__ __forceinline__ float redmax16(float v) {
    v = fmaxf(v, __shfl_xor_sync(0xffffffffu, v, 1));
    v = fmaxf(v, __shfl_xor_sync(0xffffffffu, v, 2));
    v = fmaxf(v, __shfl_xor_sync(0xffffffffu, v, 4));
    v = fmaxf(v, __shfl_xor_sync(0xffffffffu, v, 8));
    return v;
}
__device__ __forceinline__ float redsum16(float v) {
    v += __shfl_xor_sync(0xffffffffu, v, 1);
    v += __shfl_xor_sync(0xffffffffu, v, 2);
    v += __shfl_xor_sync(0xffffffffu, v, 4);
    v += __shfl_xor_sync(0xffffffffu, v, 8);
    return v;
}

__global__ __launch_bounds__(256, 2)
void attn_kernel(const float* __restrict__ Kg, const float* __restrict__ Vg)
{
    __shared__ float Qs[64][64];
    __shared__ float KP[64][64];
    __shared__ float Vs[64][64];

    const int tid = threadIdx.x;
    const int tx = tid & 15;
    const int ty = tid >> 4;
    const int qb = blockIdx.x;
    const int bh = blockIdx.y;

    const float* Qp = g_q + (size_t)bh * T_ * D_ + (size_t)qb * 64 * D_;
    const float* Kp = Kg + (size_t)bh * T_ * D_;
    const float* Vp = Vg + (size_t)bh * T_ * D_;

    const int lr = tid >> 2;
    const int lc = (tid & 3) << 4;

#pragma unroll
    for (int q = 0; q < 4; q++)
        *(float4*)&Qs[lr][lc + q * 4] = *(const float4*)(Qp + lr * D_ + lc + q * 4);

    const int i0 = ty * 4;
    const int j0 = tx * 4;
    const int d0 = tx * 4;

    float m_i[4], l_i[4], Oa[4][4];
#pragma unroll
    for (int ii = 0; ii < 4; ii++) {
        m_i[ii] = -1e30f;
        l_i[ii] = 0.f;
#pragma unroll
        for (int dd = 0; dd < 4; dd++) Oa[ii][dd] = 0.f;
    }

    for (int kb = 0; kb <= qb; kb++) {
        __syncthreads();
        {
            const float* kr = Kp + (size_t)(kb * 64 + lr) * D_ + lc;
            const float* vr = Vp + (size_t)(kb * 64 + lr) * D_ + lc;
#pragma unroll
            for (int q = 0; q < 4; q++) {
                float4 k4 = *(const float4*)(kr + q * 4);
                KP[lc + q * 4 + 0][lr] = k4.x;
                KP[lc + q * 4 + 1][lr] = k4.y;
                KP[lc + q * 4 + 2][lr] = k4.z;
                KP[lc + q * 4 + 3][lr] = k4.w;
                *(float4*)&Vs[lr][lc + q * 4] = *(const float4*)(vr + q * 4);
            }
        }
        __syncthreads();

        float S[4][4];
#pragma unroll
        for (int ii = 0; ii < 4; ii++)
#pragma unroll
            for (int jj = 0; jj < 4; jj++) S[ii][jj] = 0.f;

#pragma unroll
        for (int d = 0; d < 64; d += 4) {
            float qv[4][4], kv[4][4];
#pragma unroll
            for (int ii = 0; ii < 4; ii++)
                *(float4*)qv[ii] = *(const float4*)&Qs[i0 + ii][d];
#pragma unroll
            for (int dc = 0; dc < 4; dc++)
                *(float4*)kv[dc] = *(const float4*)&KP[d + dc][j0];
#pragma unroll
            for (int ii = 0; ii < 4; ii++)
#pragma unroll
                for (int jj = 0; jj < 4; jj++)
                    S[ii][jj] += qv[ii][0] * kv[0][jj] + qv[ii][1] * kv[1][jj]
                               + qv[ii][2] * kv[2][jj] + qv[ii][3] * kv[3][jj];
        }

        if (kb == qb) {
#pragma unroll
            for (int ii = 0; ii < 4; ii++)
#pragma unroll
                for (int jj = 0; jj < 4; jj++)
                    if (j0 + jj > i0 + ii) S[ii][jj] = -1e30f;
        }

        float alpha[4], rsum[4];
#pragma unroll
        for (int ii = 0; ii < 4; ii++) {
            float rmax = fmaxf(fmaxf(S[ii][0], S[ii][1]), fmaxf(S[ii][2], S[ii][3]));
            rmax = redmax16(rmax);
            const float mnew = fmaxf(m_i[ii], rmax);
            alpha[ii] = __expf(m_i[ii] - mnew);
            m_i[ii] = mnew;
            float s = 0.f;
#pragma unroll
            for (int jj = 0; jj < 4; jj++) {
                const float p = __expf(S[ii][jj] - mnew);
                S[ii][jj] = p;
                s += p;
            }
            rsum[ii] = redsum16(s);
        }
#pragma unroll
        for (int ii = 0; ii < 4; ii++) {
            l_i[ii] = l_i[ii] * alpha[ii] + rsum[ii];
#pragma unroll
            for (int dd = 0; dd < 4; dd++) Oa[ii][dd] *= alpha[ii];
        }

        __syncthreads();
#pragma unroll
        for (int ii = 0; ii < 4; ii++)
#pragma unroll
            for (int jj = 0; jj < 4; jj++)
                KP[i0 + ii][j0 + jj] = S[ii][jj];
        __syncthreads();

#pragma unroll
        for (int j = 0; j < 64; j += 4) {
            float pv[4][4], vv[4][4];
#pragma unroll
            for (int ii = 0; ii < 4; ii++)
                *(float4*)pv[ii] = *(const float4*)&KP[i0 + ii][j];
#pragma unroll
            for (int jc = 0; jc < 4; jc++)
                *(float4*)vv[jc] = *(const float4*)&Vs[j + jc][d0];
#pragma unroll
            for (int ii = 0; ii < 4; ii++)
#pragma unroll
                for (int dd = 0; dd < 4; dd++)
                    Oa[ii][dd] += pv[ii][0] * vv[0][dd] + pv[ii][1] * vv[1][dd]
                                + pv[ii][2] * vv[2][dd] + pv[ii][3] * vv[3][dd];
        }
    }

    const int b = bh >> 4;
    const int h = bh & 15;
#pragma unroll
    for (int ii = 0; ii < 4; ii++) {
        const float inv = 1.f / l_i[ii];
        const int t = qb * 64 + i0 + ii;
        float4 o4;
        o4.x = Oa[ii][0] * inv;
        o4.y = Oa[ii][1] * inv;
        o4.z = Oa[ii][2] * inv;
        o4.w = Oa[ii][3] * inv;
        *(float4*)&g_att[((size_t)(b * T_ + t)) * C_ + h * 64 + d0] = o4;
    }
}

// ---------------------------------------------------------------------------
// Launch. Inputs: x, mask, W_attn, b_attn, W_proj, b_proj.
// Output: [out (B,T,C) | k (B,H,T,D) | v (B,H,T,D)] fp32.
// ---------------------------------------------------------------------------
extern "C" void kernel_launch(void* const* d_in, const int* in_sizes, int n_in,
                              void* d_out, int out_size)
{
    (void)in_sizes; (void)n_in; (void)out_size;
    const float* x      = (const float*)d_in[0];
    const float* W_attn = (const float*)d_in[2];
    const float* b_attn = (const float*)d_in[3];
    const float* W_proj = (const float*)d_in[4];
    const float* b_proj = (const float*)d_in[5];

    float* out  = (float*)d_out;
    float* kout = out + (size_t)B_ * H_ * T_ * D_;
    float* vout = kout + (size_t)B_ * H_ * T_ * D_;

    cudaFuncSetAttribute(mma_gemm<0>, cudaFuncAttributeMaxDynamicSharedMemorySize,
                         SMEM_GEMM_BYTES);
    cudaFuncSetAttribute(mma_gemm<1>, cudaFuncAttributeMaxDynamicSharedMemorySize,
                         SMEM_GEMM_BYTES);

    // 1) conversions
    split_kernel<0><<<1024, 256>>>(x);
    tsplit_kernel<0><<<dim3(96, 32), dim3(32, 8)>>>(W_attn);
    tsplit_kernel<1><<<dim3(32, 32), dim3(32, 8)>>>(W_proj);

    // 2) QKV GEMM (mma.sync bf16x3) + bias + scatter
    mma_gemm<0><<<dim3(24, 64), 256, SMEM_GEMM_BYTES>>>(b_attn, nullptr, kout, vout);

    // 3) causal flash attention -> g_att
    attn_kernel<<<dim3(T_ / 64, B_ * H_), 256>>>(kout, vout);

    // 4) att output -> hi/lo, proj GEMM
    split_kernel<1><<<1024, 256>>>(nullptr);
    mma_gemm<1><<<dim3(8, 64), 256, SMEM_GEMM_BYTES>>>(b_proj, out, nullptr, nullptr);
}

// round 4
// speedup vs baseline: 3.3572x; 1.9905x over previous
#include <cuda_runtime.h>
#include <cuda_bf16.h>
#include <cstdint>

// Problem constants
#define B_ 4
#define T_ 2048
#define C_ 1024
#define H_ 16
#define D_ 64
#define BT_ (B_ * T_)            // 8192
#define KDIM 1024

#define QSCALE 0.18033688011112042f   // 0.125 * log2(e)

// ---------------------------------------------------------------------------
// Scratch (device globals — no allocation allowed)
// ---------------------------------------------------------------------------
__device__ __nv_bfloat16 g_xh[(size_t)BT_ * KDIM];    // x hi/lo
__device__ __nv_bfloat16 g_xl[(size_t)BT_ * KDIM];
__device__ __nv_bfloat16 g_wh[(size_t)3 * C_ * KDIM]; // W_attn^T hi/lo [3072][1024]
__device__ __nv_bfloat16 g_wl[(size_t)3 * C_ * KDIM];
__device__ __nv_bfloat16 g_ph[(size_t)C_ * KDIM];     // W_proj^T hi/lo [1024][1024]
__device__ __nv_bfloat16 g_pl[(size_t)C_ * KDIM];
__device__ __nv_bfloat16 g_ah[(size_t)BT_ * KDIM];    // attn-out hi/lo [B,T,C]
__device__ __nv_bfloat16 g_al[(size_t)BT_ * KDIM];
// Q/K/V bf16 hi/lo in [B,H,T,D]; q pre-scaled by QSCALE
__device__ __nv_bfloat16 g_qh[(size_t)BT_ * C_];
__device__ __nv_bfloat16 g_ql[(size_t)BT_ * C_];
__device__ __nv_bfloat16 g_kh[(size_t)BT_ * C_];
__device__ __nv_bfloat16 g_kl[(size_t)BT_ * C_];
__device__ __nv_bfloat16 g_vh[(size_t)BT_ * C_];
__device__ __nv_bfloat16 g_vl[(size_t)BT_ * C_];

// ---------------------------------------------------------------------------
// helpers (sm_80-era PTX — legal at compute_103 base)
// ---------------------------------------------------------------------------
__device__ __forceinline__ uint32_t s2u(const void* p) {
    uint32_t a;
    asm("{ .reg .u64 t; cvta.to.shared.u64 t, %1; cvt.u32.u64 %0, t; }" : "=r"(a) : "l"(p));
    return a;
}
__device__ __forceinline__ uint32_t swz(uint32_t off) {   // SW128
    return off ^ ((off >> 3) & 0x70);
}
__device__ __forceinline__ void cp_async16(uint32_t dst, const void* src) {
    asm volatile("cp.async.cg.shared.global [%0], [%1], 16;" :: "r"(dst), "l"(src) : "memory");
}
__device__ __forceinline__ void ldsm4(uint32_t* r, uint32_t addr) {
    asm volatile("ldmatrix.sync.aligned.m8n8.x4.shared.b16 {%0,%1,%2,%3}, [%4];"
                 : "=r"(r[0]), "=r"(r[1]), "=r"(r[2]), "=r"(r[3]) : "r"(addr));
}
__device__ __forceinline__ void ldsm4t(uint32_t* r, uint32_t addr) {
    asm volatile("ldmatrix.sync.aligned.m8n8.x4.trans.shared.b16 {%0,%1,%2,%3}, [%4];"
                 : "=r"(r[0]), "=r"(r[1]), "=r"(r[2]), "=r"(r[3]) : "r"(addr));
}
__device__ __forceinline__ void mma2(float* c, const uint32_t* a, uint32_t b0, uint32_t b1) {
    asm volatile(
        "mma.sync.aligned.m16n8k16.row.col.f32.bf16.bf16.f32 "
        "{%0,%1,%2,%3}, {%4,%5,%6,%7}, {%8,%9}, {%0,%1,%2,%3};"
        : "+f"(c[0]), "+f"(c[1]), "+f"(c[2]), "+f"(c[3])
        : "r"(a[0]), "r"(a[1]), "r"(a[2]), "r"(a[3]), "r"(b0), "r"(b1));
}
__device__ __forceinline__ void packsplit(float x, float y, uint32_t& hi, uint32_t& lo) {
    __nv_bfloat162 h, l;
    h.x = __float2bfloat16(x); h.y = __float2bfloat16(y);
    l.x = __float2bfloat16(x - __bfloat162float(h.x));
    l.y = __float2bfloat16(y - __bfloat162float(h.y));
    hi = *(uint32_t*)&h; lo = *(uint32_t*)&l;
}
__device__ __forceinline__ float qred_max(float v) {
    v = fmaxf(v, __shfl_xor_sync(~0u, v, 1));
    return fmaxf(v, __shfl_xor_sync(~0u, v, 2));
}
__device__ __forceinline__ float qred_sum(float v) {
    v += __shfl_xor_sync(~0u, v, 1);
    return v + __shfl_xor_sync(~0u, v, 2);
}

// ---------------------------------------------------------------------------
// Conversion kernels
// ---------------------------------------------------------------------------
__global__ void split_x(const float* __restrict__ s)
{
    const size_t n4 = (size_t)BT_ * KDIM / 4;
    for (size_t i = (size_t)blockIdx.x * blockDim.x + threadIdx.x; i < n4;
         i += (size_t)gridDim.x * blockDim.x) {
        float4 v = ((const float4*)s)[i];
        uint32_t h0, l0, h1, l1;
        packsplit(v.x, v.y, h0, l0);
        packsplit(v.z, v.w, h1, l1);
        ((uint32_t*)g_xh)[2 * i] = h0; ((uint32_t*)g_xh)[2 * i + 1] = h1;
        ((uint32_t*)g_xl)[2 * i] = l0; ((uint32_t*)g_xl)[2 * i + 1] = l1;
    }
}

// fp32 W [K=1024, NC] row-major -> transposed hi/lo bf16 [NC, 1024]
template <int W>
__global__ void tsplit_kernel(const float* __restrict__ src)
{
    constexpr int NC = (W == 0) ? 3 * C_ : C_;
    __nv_bfloat16* dh = (W == 0) ? g_wh : g_ph;
    __nv_bfloat16* dl = (W == 0) ? g_wl : g_pl;
    __shared__ float tile[32][33];
    const int x = blockIdx.x * 32 + threadIdx.x;
    const int y0 = blockIdx.y * 32;
#pragma unroll
    for (int j = 0; j < 32; j += 8)
        tile[threadIdx.y + j][threadIdx.x] = src[(size_t)(y0 + threadIdx.y + j) * NC + x];
    __syncthreads();
    const int ox = y0 + threadIdx.x;
    const int oyb = blockIdx.x * 32;
#pragma unroll
    for (int j = 0; j < 32; j += 8) {
        float v = tile[threadIdx.x][threadIdx.y + j];
        __nv_bfloat16 hh = __float2bfloat16(v);
        dh[(size_t)(oyb + threadIdx.y + j) * KDIM + ox] = hh;
        dl[(size_t)(oyb + threadIdx.y + j) * KDIM + ox] =
            __float2bfloat16(v - __bfloat162float(hh));
    }
}

// ---------------------------------------------------------------------------
// bf16x3 GEMM via mma.sync (as R3) with dual-write epilogue for q/k/v.
// ---------------------------------------------------------------------------
#define SM_STAGE 65536
#define SMEM_GEMM_BYTES 196608   // 3 stages

template <int MODE>
__global__ __launch_bounds__(256, 1)
void mma_gemm(const float* __restrict__ bias,
              float* __restrict__ o0, float* __restrict__ o1, float* __restrict__ o2)
{
    extern __shared__ __align__(1024) char smem[];
    const uint32_t sm = s2u(smem);
    const int tid = threadIdx.x;
    const int wid = tid >> 5;
    const int lid = tid & 31;
    const int n0 = blockIdx.x * 128;
    const int m0 = blockIdx.y * 128;

    const __nv_bfloat16* Ahp = (MODE == 0) ? g_xh : g_ah;
    const __nv_bfloat16* Alp = (MODE == 0) ? g_xl : g_al;
    const __nv_bfloat16* Bhp = (MODE == 0) ? g_wh : g_ph;
    const __nv_bfloat16* Blp = (MODE == 0) ? g_wl : g_pl;

    const __nv_bfloat16* srcs[16];
    uint32_t dsts[16];
#pragma unroll
    for (int r = 0; r < 16; r++) {
        const int id = tid + r * 256;
        const int bsel = id >> 10;
        const int row = (id >> 3) & 127;
        const int c16 = id & 7;
        dsts[r] = (uint32_t)(bsel * 16384) + swz((uint32_t)(row * 128 + c16 * 16));
        const __nv_bfloat16* base;
        if (bsel == 0)      base = Ahp + (size_t)(m0 + row) * KDIM;
        else if (bsel == 1) base = Alp + (size_t)(m0 + row) * KDIM;
        else if (bsel == 2) base = Bhp + (size_t)(n0 + row) * KDIM;
        else                base = Blp + (size_t)(n0 + row) * KDIM;
        srcs[r] = base + c16 * 8;
    }
    auto issue_loads = [&](int c, int s) {
        const uint32_t sb = sm + (uint32_t)s * SM_STAGE;
#pragma unroll
        for (int r = 0; r < 16; r++)
            cp_async16(sb + dsts[r], srcs[r] + c * 64);
        asm volatile("cp.async.commit_group;" ::: "memory");
    };

    const int warpM = (wid & 1) * 64;
    const int warpN = (wid >> 1) * 32;
    const int g = lid >> 2;
    const int tig = lid & 3;
    const int aRow = lid & 15;
    const int aKb = (lid >> 4) * 16;
    const int bRow = ((lid >> 4) & 1) * 8 + (lid & 7);
    const int bKb = ((lid >> 3) & 1) * 16;

    float Cr[4][4][4];
#pragma unroll
    for (int mi = 0; mi < 4; mi++)
#pragma unroll
        for (int j = 0; j < 4; j++)
#pragma unroll
            for (int qi = 0; qi < 4; qi++) Cr[mi][j][qi] = 0.f;

    issue_loads(0, 0);
    issue_loads(1, 1);

    for (int c = 0; c < 16; c++) {
        const int s = c % 3;
        if (c < 15) asm volatile("cp.async.wait_group 1;" ::: "memory");
        else        asm volatile("cp.async.wait_group 0;" ::: "memory");
        __syncthreads();

        const uint32_t sb = sm + (uint32_t)s * SM_STAGE;
        const uint32_t tAh = sb, tAl = sb + 16384, tBh = sb + 32768, tBl = sb + 49152;

#pragma unroll
        for (int ks = 0; ks < 4; ks++) {
            const int kb = ks * 32;
            uint32_t ah[4][4], al[4][4], bh[2][4], bl[2][4];
#pragma unroll
            for (int mi = 0; mi < 4; mi++) {
                const uint32_t off = swz((uint32_t)((warpM + mi * 16 + aRow) * 128 + kb + aKb));
                ldsm4(ah[mi], tAh + off);
                ldsm4(al[mi], tAl + off);
            }
#pragma unroll
            for (int jp = 0; jp < 2; jp++) {
                const uint32_t off = swz((uint32_t)((warpN + jp * 16 + bRow) * 128 + kb + bKb));
                ldsm4(bh[jp], tBh + off);
                ldsm4(bl[jp], tBl + off);
            }
#pragma unroll
            for (int mi = 0; mi < 4; mi++)
#pragma unroll
                for (int j = 0; j < 4; j++) {
                    const int jp = j >> 1, o = (j & 1) * 2;
                    mma2(Cr[mi][j], ah[mi], bh[jp][o], bh[jp][o + 1]);
                    mma2(Cr[mi][j], ah[mi], bl[jp][o], bl[jp][o + 1]);
                    mma2(Cr[mi][j], al[mi], bh[jp][o], bh[jp][o + 1]);
                }
        }
        __syncthreads();
        if (c + 2 < 16) issue_loads(c + 2, (c + 2) % 3);
    }

    // ---- epilogue ----
#pragma unroll
    for (int mi = 0; mi < 4; mi++)
#pragma unroll
        for (int j = 0; j < 4; j++) {
            const int col = n0 + warpN + j * 8 + tig * 2;
            const float2 bb = *(const float2*)(bias + col);
#pragma unroll
            for (int half = 0; half < 2; half++) {
                const int row = m0 + warpM + mi * 16 + g + half * 8;
                float2 v;
                v.x = Cr[mi][j][half * 2 + 0] + bb.x;
                v.y = Cr[mi][j][half * 2 + 1] + bb.y;
                if (MODE == 0) {
                    const int seg = col >> 10;
                    const int c0 = col & 1023;
                    const int h = c0 >> 6;
                    const int dd = c0 & 63;
                    const int b = row >> 11;
                    const int t = row & (T_ - 1);
                    const size_t idx = ((size_t)(b * H_ + h) * T_ + t) * D_ + dd;
                    uint32_t hi, lo;
                    if (seg == 0) {
                        packsplit(v.x * QSCALE, v.y * QSCALE, hi, lo);
                        *(uint32_t*)&g_qh[idx] = hi;
                        *(uint32_t*)&g_ql[idx] = lo;
                    } else if (seg == 1) {
                        *(float2*)&o1[idx] = v;
                        packsplit(v.x, v.y, hi, lo);
                        *(uint32_t*)&g_kh[idx] = hi;
                        *(uint32_t*)&g_kl[idx] = lo;
                    } else {
                        *(float2*)&o2[idx] = v;
                        packsplit(v.x, v.y, hi, lo);
                        *(uint32_t*)&g_vh[idx] = hi;
                        *(uint32_t*)&g_vl[idx] = lo;
                    }
                } else {
                    *(float2*)&o0[(size_t)row * C_ + col] = v;
                }
            }
        }
}

// ---------------------------------------------------------------------------
// Flash attention via mma.sync bf16x3.
// CTA: 128 q-rows of one (b,h); kv tiles 64; 8 warps x 16 rows; 3-stage pipe.
// smem: Qh/Ql 16KB each @0/16384; stages s @32768+s*32768: Kh,Kl,Vh,Vl 8KB each
// ---------------------------------------------------------------------------
#define AT_SMEM 131072

__global__ __launch_bounds__(256, 1)
void attn_mma()
{
    extern __shared__ __align__(1024) char smem[];
    const uint32_t sm = s2u(smem);
    const int tid = threadIdx.x;
    const int wid = tid >> 5;
    const int lid = tid & 31;
    const int qb = 15 - blockIdx.x;          // heavy CTAs first
    const int bh = blockIdx.y;
    const size_t base_qkv = (size_t)bh * T_ * D_;
    const int nt = 2 * qb + 2;

    // Q loads (part of group 0)
#pragma unroll
    for (int r = 0; r < 8; r++) {
        const int id = tid + r * 256;
        const int bsel = id >> 10;
        const int row = (id >> 3) & 127;
        const int c16 = id & 7;
        const uint32_t dst = sm + bsel * 16384 + swz((uint32_t)(row * 128 + c16 * 16));
        const __nv_bfloat16* src = (bsel ? g_ql : g_qh) + base_qkv
                                   + (size_t)(qb * 128 + row) * D_ + c16 * 8;
        cp_async16(dst, src);
    }
    auto issue_kv = [&](int kt, int s) {
        const uint32_t sb = sm + 32768 + (uint32_t)s * 32768;
#pragma unroll
        for (int r = 0; r < 8; r++) {
            const int id = tid + r * 256;
            const int bsel = id >> 9;        // 0 Kh 1 Kl 2 Vh 3 Vl
            const int row = (id >> 3) & 63;
            const int c16 = id & 7;
            const uint32_t dst = sb + bsel * 8192 + swz((uint32_t)(row * 128 + c16 * 16));
            const __nv_bfloat16* src;
            if (bsel == 0)      src = g_kh;
            else if (bsel == 1) src = g_kl;
            else if (bsel == 2) src = g_vh;
            else                src = g_vl;
            src += base_qkv + (size_t)(kt * 64 + row) * D_ + c16 * 8;
            cp_async16(dst, src);
        }
        asm volatile("cp.async.commit_group;" ::: "memory");
    };
    issue_kv(0, 0);      // commits Q + KV0 as group 0
    issue_kv(1, 1);      // group 1 (nt >= 2 always)

    const int g = lid >> 2;
    const int t2 = (lid & 3) * 2;
    const int lrow16 = lid & 15;
    const int lhi = (lid >> 4) * 16;

    uint32_t qh[4][4], ql[4][4];
    float cfr[8][4], ofr[8][4];
    float mrow0 = -1e30f, mrow1 = -1e30f, lrow0 = 0.f, lrow1 = 0.f;
#pragma unroll
    for (int j = 0; j < 8; j++)
#pragma unroll
        for (int qi = 0; qi < 4; qi++) ofr[j][qi] = 0.f;

    for (int kb = 0; kb < nt; kb++) {
        const int s = kb % 3;
        if (kb + 2 < nt) asm volatile("cp.async.wait_group 1;" ::: "memory");
        else             asm volatile("cp.async.wait_group 0;" ::: "memory");
        __syncthreads();
        if (kb == 0) {
#pragma unroll
            for (int kc = 0; kc < 4; kc++) {
                const uint32_t off = swz((uint32_t)((wid * 16 + lrow16) * 128 + kc * 32 + lhi));
                ldsm4(qh[kc], sm + off);
                ldsm4(ql[kc], sm + 16384 + off);
            }
        }
        const uint32_t kvb = sm + 32768 + (uint32_t)s * 32768;

        // ---- S = Q K^T ----
#pragma unroll
        for (int j = 0; j < 8; j++)
#pragma unroll
            for (int qi = 0; qi < 4; qi++) cfr[j][qi] = 0.f;
#pragma unroll
        for (int kc = 0; kc < 4; kc++) {
            uint32_t kh4[4][4], kl4[4][4];
#pragma unroll
            for (int jp = 0; jp < 4; jp++) {
                const uint32_t off = swz((uint32_t)((jp * 16 + lrow16) * 128 + kc * 32 + lhi));
                ldsm4(kh4[jp], kvb + off);
                ldsm4(kl4[jp], kvb + 8192 + off);
            }
#pragma unroll
            for (int jp = 0; jp < 4; jp++) {
                mma2(cfr[2 * jp],     qh[kc], kh4[jp][0], kh4[jp][2]);
                mma2(cfr[2 * jp],     qh[kc], kl4[jp][0], kl4[jp][2]);
                mma2(cfr[2 * jp],     ql[kc], kh4[jp][0], kh4[jp][2]);
                mma2(cfr[2 * jp + 1], qh[kc], kh4[jp][1], kh4[jp][3]);
                mma2(cfr[2 * jp + 1], qh[kc], kl4[jp][1], kl4[jp][3]);
                mma2(cfr[2 * jp + 1], ql[kc], kh4[jp][1], kh4[jp][3]);
            }
        }

        // ---- causal mask (diagonal tiles only) ----
        if (kb >= 2 * qb) {
            const int qr = qb * 128 + wid * 16 + g;
            const int kv0 = kb * 64;
#pragma unroll
            for (int j = 0; j < 8; j++) {
                const int col = kv0 + j * 8 + t2;
#pragma unroll
                for (int qi = 0; qi < 4; qi++) {
                    const int row = qr + ((qi >> 1) << 3);
                    if (col + (qi & 1) > row) cfr[j][qi] = -1e30f;
                }
            }
        }

        // ---- online softmax (log2 domain) ----
        float mx0 = -1e30f, mx1 = -1e30f;
#pragma unroll
        for (int j = 0; j < 8; j++) {
            mx0 = fmaxf(mx0, fmaxf(cfr[j][0], cfr[j][1]));
            mx1 = fmaxf(mx1, fmaxf(cfr[j][2], cfr[j][3]));
        }
        mx0 = qred_max(mx0);
        mx1 = qred_max(mx1);
        const float mn0 = fmaxf(mrow0, mx0), mn1 = fmaxf(mrow1, mx1);
        const float al0 = exp2f(mrow0 - mn0), al1 = exp2f(mrow1 - mn1);
        mrow0 = mn0; mrow1 = mn1;
        float s0 = 0.f, s1 = 0.f;
#pragma unroll
        for (int j = 0; j < 8; j++) {
            cfr[j][0] = exp2f(cfr[j][0] - mn0);
            cfr[j][1] = exp2f(cfr[j][1] - mn0);
            cfr[j][2] = exp2f(cfr[j][2] - mn1);
            cfr[j][3] = exp2f(cfr[j][3] - mn1);
            s0 += cfr[j][0] + cfr[j][1];
            s1 += cfr[j][2] + cfr[j][3];
        }
        s0 = qred_sum(s0);
        s1 = qred_sum(s1);
        lrow0 = lrow0 * al0 + s0;
        lrow1 = lrow1 * al1 + s1;
#pragma unroll
        for (int j = 0; j < 8; j++) {
            ofr[j][0] *= al0; ofr[j][1] *= al0;
            ofr[j][2] *= al1; ofr[j][3] *= al1;
        }

        // ---- O += P V ----
#pragma unroll
        for (int kc = 0; kc < 4; kc++) {
            uint32_t ph[4], pl[4];
            packsplit(cfr[2 * kc][0],     cfr[2 * kc][1],     ph[0], pl[0]);
            packsplit(cfr[2 * kc][2],     cfr[2 * kc][3],     ph[1], pl[1]);
            packsplit(cfr[2 * kc + 1][0], cfr[2 * kc + 1][1], ph[2], pl[2]);
            packsplit(cfr[2 * kc + 1][2], cfr[2 * kc + 1][3], ph[3], pl[3]);
#pragma unroll
            for (int nc = 0; nc < 4; nc++) {
                uint32_t vh4[4], vl4[4];
                const uint32_t off = swz((uint32_t)((kc * 16 + lrow16) * 128 + nc * 32 + lhi));
                ldsm4t(vh4, kvb + 16384 + off);
                ldsm4t(vl4, kvb + 24576 + off);
                mma2(ofr[2 * nc],     ph, vh4[0], vh4[1]);
                mma2(ofr[2 * nc],     ph, vl4[0], vl4[1]);
                mma2(ofr[2 * nc],     pl, vh4[0], vh4[1]);
                mma2(ofr[2 * nc + 1], ph, vh4[2], vh4[3]);
                mma2(ofr[2 * nc + 1], ph, vl4[2], vl4[3]);
                mma2(ofr[2 * nc + 1], pl, vh4[2], vh4[3]);
            }
        }
        if (kb + 2 < nt) issue_kv(kb + 2, (kb + 2) % 3);
    }

    // ---- epilogue: write hi/lo bf16 into [B,T,C] for proj GEMM ----
    const float inv0 = 1.f / lrow0, inv1 = 1.f / lrow1;
    const int b = bh >> 4, h = bh & 15;
    const int t0 = qb * 128 + wid * 16 + g;
#pragma unroll
    for (int j = 0; j < 8; j++) {
        const int d = j * 8 + t2;
        const size_t i0 = ((size_t)(b * T_ + t0)) * C_ + h * 64 + d;
        const size_t i1 = i0 + (size_t)8 * C_;
        uint32_t hi, lo;
        packsplit(ofr[j][0] * inv0, ofr[j][1] * inv0, hi, lo);
        *(uint32_t*)&g_ah[i0] = hi;
        *(uint32_t*)&g_al[i0] = lo;
        packsplit(ofr[j][2] * inv1, ofr[j][3] * inv1, hi, lo);
        *(uint32_t*)&g_ah[i1] = hi;
        *(uint32_t*)&g_al[i1] = lo;
    }
}

// ---------------------------------------------------------------------------
// Launch. Inputs: x, mask, W_attn, b_attn, W_proj, b_proj.
// Output: [out (B,T,C) | k (B,H,T,D) | v (B,H,T,D)] fp32.
// ---------------------------------------------------------------------------
extern "C" void kernel_launch(void* const* d_in, const int* in_sizes, int n_in,
                              void* d_out, int out_size)
{
    (void)in_sizes; (void)n_in; (void)out_size;
    const float* x      = (const float*)d_in[0];
    const float* W_attn = (const float*)d_in[2];
    const float* b_attn = (const float*)d_in[3];
    const float* W_proj = (const float*)d_in[4];
    const float* b_proj = (const float*)d_in[5];

    float* out  = (float*)d_out;
    float* kout = out + (size_t)B_ * H_ * T_ * D_;
    float* vout = kout + (size_t)B_ * H_ * T_ * D_;

    cudaFuncSetAttribute(mma_gemm<0>, cudaFuncAttributeMaxDynamicSharedMemorySize,
                         SMEM_GEMM_BYTES);
    cudaFuncSetAttribute(mma_gemm<1>, cudaFuncAttributeMaxDynamicSharedMemorySize,
                         SMEM_GEMM_BYTES);
    cudaFuncSetAttribute(attn_mma, cudaFuncAttributeMaxDynamicSharedMemorySize,
                         AT_SMEM);

    // 1) conversions
    split_x<<<1024, 256>>>(x);
    tsplit_kernel<0><<<dim3(96, 32), dim3(32, 8)>>>(W_attn);
    tsplit_kernel<1><<<dim3(32, 32), dim3(32, 8)>>>(W_proj);

    // 2) QKV GEMM + bias + dual-write scatter
    mma_gemm<0><<<dim3(24, 64), 256, SMEM_GEMM_BYTES>>>(b_attn, nullptr, kout, vout);

    // 3) causal flash attention (tensor cores) -> g_ah/g_al
    attn_mma<<<dim3(16, 64), 256, AT_SMEM>>>();

    // 4) proj GEMM
    mma_gemm<1><<<dim3(8, 64), 256, SMEM_GEMM_BYTES>>>(b_proj, out, nullptr, nullptr);
}

// round 5
// speedup vs baseline: 4.6012x; 1.3706x over previous
#include <cuda_runtime.h>
#include <cuda_fp16.h>
#include <cstdint>

// Problem constants
#define B_ 4
#define T_ 2048
#define C_ 1024
#define H_ 16
#define D_ 64
#define BT_ (B_ * T_)            // 8192
#define KDIM 1024

#define QSCALE 0.18033688011112042f   // 0.125 * log2(e)

// ---------------------------------------------------------------------------
// Scratch (device globals — no allocation allowed). All splits fp16 hi/lo.
// ---------------------------------------------------------------------------
__device__ __half g_xh[(size_t)BT_ * KDIM];    // x hi/lo
__device__ __half g_xl[(size_t)BT_ * KDIM];
__device__ __half g_wh[(size_t)3 * C_ * KDIM]; // W_attn^T hi [3072][1024]
__device__ __half g_ph[(size_t)C_ * KDIM];     // W_proj^T hi [1024][1024]
__device__ __half g_ah[(size_t)BT_ * KDIM];    // attn-out hi/lo [B,T,C]
__device__ __half g_al[(size_t)BT_ * KDIM];
// Q hi/lo, K hi, V hi in [B,H,T,D]; q pre-scaled by QSCALE
__device__ __half g_qh[(size_t)BT_ * C_];
__device__ __half g_ql[(size_t)BT_ * C_];
__device__ __half g_kh[(size_t)BT_ * C_];
__device__ __half g_vh[(size_t)BT_ * C_];

// ---------------------------------------------------------------------------
// helpers (sm_80-era PTX — legal at compute_103 base)
// ---------------------------------------------------------------------------
__device__ __forceinline__ uint32_t s2u(const void* p) {
    uint32_t a;
    asm("{ .reg .u64 t; cvta.to.shared.u64 t, %1; cvt.u32.u64 %0, t; }" : "=r"(a) : "l"(p));
    return a;
}
__device__ __forceinline__ uint32_t swz(uint32_t off) {   // SW128
    return off ^ ((off >> 3) & 0x70);
}
__device__ __forceinline__ void cp_async16(uint32_t dst, const void* src) {
    asm volatile("cp.async.cg.shared.global [%0], [%1], 16;" :: "r"(dst), "l"(src) : "memory");
}
__device__ __forceinline__ void ldsm4(uint32_t* r, uint32_t addr) {
    asm volatile("ldmatrix.sync.aligned.m8n8.x4.shared.b16 {%0,%1,%2,%3}, [%4];"
                 : "=r"(r[0]), "=r"(r[1]), "=r"(r[2]), "=r"(r[3]) : "r"(addr));
}
__device__ __forceinline__ void ldsm4t(uint32_t* r, uint32_t addr) {
    asm volatile("ldmatrix.sync.aligned.m8n8.x4.trans.shared.b16 {%0,%1,%2,%3}, [%4];"
                 : "=r"(r[0]), "=r"(r[1]), "=r"(r[2]), "=r"(r[3]) : "r"(addr));
}
__device__ __forceinline__ void mma2(float* c, const uint32_t* a, uint32_t b0, uint32_t b1) {
    asm volatile(
        "mma.sync.aligned.m16n8k16.row.col.f32.f16.f16.f32 "
        "{%0,%1,%2,%3}, {%4,%5,%6,%7}, {%8,%9}, {%0,%1,%2,%3};"
        : "+f"(c[0]), "+f"(c[1]), "+f"(c[2]), "+f"(c[3])
        : "r"(a[0]), "r"(a[1]), "r"(a[2]), "r"(a[3]), "r"(b0), "r"(b1));
}
__device__ __forceinline__ uint32_t packh2(float x, float y) {
    __half2 t; t.x = __float2half(x); t.y = __float2half(y);
    return *(uint32_t*)&t;
}
__device__ __forceinline__ void packsplit(float x, float y, uint32_t& hi, uint32_t& lo) {
    __half2 h, l;
    h.x = __float2half(x); h.y = __float2half(y);
    l.x = __float2half(x - __half2float(h.x));
    l.y = __float2half(y - __half2float(h.y));
    hi = *(uint32_t*)&h; lo = *(uint32_t*)&l;
}
__device__ __forceinline__ float qred_max(float v) {
    v = fmaxf(v, __shfl_xor_sync(~0u, v, 1));
    return fmaxf(v, __shfl_xor_sync(~0u, v, 2));
}
__device__ __forceinline__ float qred_sum(float v) {
    v += __shfl_xor_sync(~0u, v, 1);
    return v + __shfl_xor_sync(~0u, v, 2);
}

// ---------------------------------------------------------------------------
// Conversion kernels
// ---------------------------------------------------------------------------
__global__ void split_x(const float* __restrict__ s)
{
    const size_t n4 = (size_t)BT_ * KDIM / 4;
    for (size_t i = (size_t)blockIdx.x * blockDim.x + threadIdx.x; i < n4;
         i += (size_t)gridDim.x * blockDim.x) {
        float4 v = ((const float4*)s)[i];
        uint32_t h0, l0, h1, l1;
        packsplit(v.x, v.y, h0, l0);
        packsplit(v.z, v.w, h1, l1);
        ((uint32_t*)g_xh)[2 * i] = h0; ((uint32_t*)g_xh)[2 * i + 1] = h1;
        ((uint32_t*)g_xl)[2 * i] = l0; ((uint32_t*)g_xl)[2 * i + 1] = l1;
    }
}

// fp32 W [K=1024, NC] row-major -> transposed fp16 hi [NC, 1024]
template <int W>
__global__ void tsplit_kernel(const float* __restrict__ src)
{
    constexpr int NC = (W == 0) ? 3 * C_ : C_;
    __half* dh = (W == 0) ? g_wh : g_ph;
    __shared__ float tile[32][33];
    const int x = blockIdx.x * 32 + threadIdx.x;
    const int y0 = blockIdx.y * 32;
#pragma unroll
    for (int j = 0; j < 32; j += 8)
        tile[threadIdx.y + j][threadIdx.x] = src[(size_t)(y0 + threadIdx.y + j) * NC + x];
    __syncthreads();
    const int ox = y0 + threadIdx.x;
    const int oyb = blockIdx.x * 32;
#pragma unroll
    for (int j = 0; j < 32; j += 8)
        dh[(size_t)(oyb + threadIdx.y + j) * KDIM + ox] =
            __float2half(tile[threadIdx.x][threadIdx.y + j]);
}

// ---------------------------------------------------------------------------
// fp16x2 GEMM via mma.sync: D = A x B^T, A split hi/lo, B hi only.
// CTA 128x128, K_chunk=64, 3-stage cp.async, stage = [Ah 16K][Al 16K][Bh 16K].
// ---------------------------------------------------------------------------
#define SM_STAGE 49152
#define SMEM_GEMM_BYTES 147456   // 3 stages

template <int MODE>
__global__ __launch_bounds__(256, 1)
void mma_gemm(const float* __restrict__ bias,
              float* __restrict__ o0, float* __restrict__ o1, float* __restrict__ o2)
{
    extern __shared__ __align__(1024) char smem[];
    const uint32_t sm = s2u(smem);
    const int tid = threadIdx.x;
    const int wid = tid >> 5;
    const int lid = tid & 31;
    const int n0 = blockIdx.x * 128;
    const int m0 = blockIdx.y * 128;

    const __half* Ahp = (MODE == 0) ? g_xh : g_ah;
    const __half* Alp = (MODE == 0) ? g_xl : g_al;
    const __half* Bhp = (MODE == 0) ? g_wh : g_ph;

    // copy plan: 3072 x 16B per stage, 12 per thread
    const __half* srcs[12];
    uint32_t dsts[12];
#pragma unroll
    for (int r = 0; r < 12; r++) {
        const int id = tid + r * 256;
        const int bsel = id >> 10;           // 0:Ah 1:Al 2:Bh
        const int row = (id >> 3) & 127;
        const int c16 = id & 7;
        dsts[r] = (uint32_t)(bsel * 16384) + swz((uint32_t)(row * 128 + c16 * 16));
        const __half* base;
        if (bsel == 0)      base = Ahp + (size_t)(m0 + row) * KDIM;
        else if (bsel == 1) base = Alp + (size_t)(m0 + row) * KDIM;
        else                base = Bhp + (size_t)(n0 + row) * KDIM;
        srcs[r] = base + c16 * 8;
    }
    auto issue_loads = [&](int c, int s) {
        const uint32_t sb = sm + (uint32_t)s * SM_STAGE;
#pragma unroll
        for (int r = 0; r < 12; r++)
            cp_async16(sb + dsts[r], srcs[r] + c * 64);
        asm volatile("cp.async.commit_group;" ::: "memory");
    };

    const int warpM = (wid & 1) * 64;
    const int warpN = (wid >> 1) * 32;
    const int g = lid >> 2;
    const int tig = lid & 3;
    const int aRow = lid & 15;
    const int aKb = (lid >> 4) * 16;
    const int bRow = ((lid >> 4) & 1) * 8 + (lid & 7);
    const int bKb = ((lid >> 3) & 1) * 16;

    float Cr[4][4][4];
#pragma unroll
    for (int mi = 0; mi < 4; mi++)
#pragma unroll
        for (int j = 0; j < 4; j++)
#pragma unroll
            for (int qi = 0; qi < 4; qi++) Cr[mi][j][qi] = 0.f;

    issue_loads(0, 0);
    issue_loads(1, 1);

    for (int c = 0; c < 16; c++) {
        const int s = c % 3;
        if (c < 15) asm volatile("cp.async.wait_group 1;" ::: "memory");
        else        asm volatile("cp.async.wait_group 0;" ::: "memory");
        __syncthreads();
        // stage (c+2)%3 == (c-1)%3; all reads of it finished before this sync
        if (c + 2 < 16) issue_loads(c + 2, (c + 2) % 3);

        const uint32_t sb = sm + (uint32_t)s * SM_STAGE;
        const uint32_t tAh = sb, tAl = sb + 16384, tBh = sb + 32768;

#pragma unroll
        for (int ks = 0; ks < 4; ks++) {
            const int kb = ks * 32;
            uint32_t ah[4][4], al[4][4], bh[2][4];
#pragma unroll
            for (int mi = 0; mi < 4; mi++) {
                const uint32_t off = swz((uint32_t)((warpM + mi * 16 + aRow) * 128 + kb + aKb));
                ldsm4(ah[mi], tAh + off);
                ldsm4(al[mi], tAl + off);
            }
#pragma unroll
            for (int jp = 0; jp < 2; jp++) {
                const uint32_t off = swz((uint32_t)((warpN + jp * 16 + bRow) * 128 + kb + bKb));
                ldsm4(bh[jp], tBh + off);
            }
#pragma unroll
            for (int mi = 0; mi < 4; mi++)
#pragma unroll
                for (int j = 0; j < 4; j++) {
                    const int jp = j >> 1, o = (j & 1) * 2;
                    mma2(Cr[mi][j], ah[mi], bh[jp][o], bh[jp][o + 1]);
                    mma2(Cr[mi][j], al[mi], bh[jp][o], bh[jp][o + 1]);
                }
        }
    }

    // ---- epilogue ----
#pragma unroll
    for (int mi = 0; mi < 4; mi++)
#pragma unroll
        for (int j = 0; j < 4; j++) {
            const int col = n0 + warpN + j * 8 + tig * 2;
            const float2 bb = *(const float2*)(bias + col);
#pragma unroll
            for (int half = 0; half < 2; half++) {
                const int row = m0 + warpM + mi * 16 + g + half * 8;
                float2 v;
                v.x = Cr[mi][j][half * 2 + 0] + bb.x;
                v.y = Cr[mi][j][half * 2 + 1] + bb.y;
                if (MODE == 0) {
                    const int seg = col >> 10;
                    const int c0 = col & 1023;
                    const int h = c0 >> 6;
                    const int dd = c0 & 63;
                    const int b = row >> 11;
                    const int t = row & (T_ - 1);
                    const size_t idx = ((size_t)(b * H_ + h) * T_ + t) * D_ + dd;
                    if (seg == 0) {
                        uint32_t hi, lo;
                        packsplit(v.x * QSCALE, v.y * QSCALE, hi, lo);
                        *(uint32_t*)&g_qh[idx] = hi;
                        *(uint32_t*)&g_ql[idx] = lo;
                    } else if (seg == 1) {
                        *(float2*)&o1[idx] = v;
                        *(uint32_t*)&g_kh[idx] = packh2(v.x, v.y);
                    } else {
                        *(float2*)&o2[idx] = v;
                        *(uint32_t*)&g_vh[idx] = packh2(v.x, v.y);
                    }
                } else {
                    *(float2*)&o0[(size_t)row * C_ + col] = v;
                }
            }
        }
}

// ---------------------------------------------------------------------------
// Flash attention via mma.sync fp16x2.
// CTA: 128 q-rows; kv tiles 64; 8 warps x 16 rows; 3-stage pipeline.
// smem: Qh/Ql 16KB @0/16384; stage s @32768+s*16384: [Kh 8KB][Vh 8KB]
// ---------------------------------------------------------------------------
#define AT_SMEM 81920

__global__ __launch_bounds__(256, 1)
void attn_mma()
{
    extern __shared__ __align__(1024) char smem[];
    const uint32_t sm = s2u(smem);
    const int tid = threadIdx.x;
    const int wid = tid >> 5;
    const int lid = tid & 31;
    const int qb = 15 - blockIdx.x;          // heavy CTAs first
    const int bh = blockIdx.y;
    const size_t base_qkv = (size_t)bh * T_ * D_;
    const int nt = 2 * qb + 2;

    // Q loads (folded into group 0)
#pragma unroll
    for (int r = 0; r < 8; r++) {
        const int id = tid + r * 256;
        const int bsel = id >> 10;
        const int row = (id >> 3) & 127;
        const int c16 = id & 7;
        const uint32_t dst = sm + bsel * 16384 + swz((uint32_t)(row * 128 + c16 * 16));
        const __half* src = (bsel ? g_ql : g_qh) + base_qkv
                            + (size_t)(qb * 128 + row) * D_ + c16 * 8;
        cp_async16(dst, src);
    }
    auto issue_kv = [&](int kt, int s) {
        const uint32_t sb = sm + 32768 + (uint32_t)s * 16384;
#pragma unroll
        for (int r = 0; r < 4; r++) {
            const int id = tid + r * 256;
            const int bsel = id >> 9;        // 0 Kh 1 Vh
            const int row = (id >> 3) & 63;
            const int c16 = id & 7;
            const uint32_t dst = sb + bsel * 8192 + swz((uint32_t)(row * 128 + c16 * 16));
            const __half* src = (bsel ? g_vh : g_kh) + base_qkv
                                + (size_t)(kt * 64 + row) * D_ + c16 * 8;
            cp_async16(dst, src);
        }
        asm volatile("cp.async.commit_group;" ::: "memory");
    };
    issue_kv(0, 0);
    issue_kv(1, 1);

    const int g = lid >> 2;
    const int t2 = (lid & 3) * 2;
    const int lrow16 = lid & 15;
    const int lhi = (lid >> 4) * 16;

    uint32_t qh[4][4], ql[4][4];
    float cfr[8][4], ofr[8][4];
    float mrow0 = -1e30f, mrow1 = -1e30f, lrow0 = 0.f, lrow1 = 0.f;
#pragma unroll
    for (int j = 0; j < 8; j++)
#pragma unroll
        for (int qi = 0; qi < 4; qi++) ofr[j][qi] = 0.f;

    for (int kb = 0; kb < nt; kb++) {
        const int s = kb % 3;
        if (kb + 2 < nt) asm volatile("cp.async.wait_group 1;" ::: "memory");
        else             asm volatile("cp.async.wait_group 0;" ::: "memory");
        __syncthreads();
        if (kb + 2 < nt) issue_kv(kb + 2, (kb + 2) % 3);
        if (kb == 0) {
#pragma unroll
            for (int kc = 0; kc < 4; kc++) {
                const uint32_t off = swz((uint32_t)((wid * 16 + lrow16) * 128 + kc * 32 + lhi));
                ldsm4(qh[kc], sm + off);
                ldsm4(ql[kc], sm + 16384 + off);
            }
        }
        const uint32_t kvb = sm + 32768 + (uint32_t)s * 16384;

        // ---- S = Q K^T ----
#pragma unroll
        for (int j = 0; j < 8; j++)
#pragma unroll
            for (int qi = 0; qi < 4; qi++) cfr[j][qi] = 0.f;
#pragma unroll
        for (int kc = 0; kc < 4; kc++) {
            uint32_t kh4[4][4];
#pragma unroll
            for (int jp = 0; jp < 4; jp++) {
                const uint32_t off = swz((uint32_t)((jp * 16 + lrow16) * 128 + kc * 32 + lhi));
                ldsm4(kh4[jp], kvb + off);
            }
#pragma unroll
            for (int jp = 0; jp < 4; jp++) {
                mma2(cfr[2 * jp],     qh[kc], kh4[jp][0], kh4[jp][2]);
                mma2(cfr[2 * jp],     ql[kc], kh4[jp][0], kh4[jp][2]);
                mma2(cfr[2 * jp + 1], qh[kc], kh4[jp][1], kh4[jp][3]);
                mma2(cfr[2 * jp + 1], ql[kc], kh4[jp][1], kh4[jp][3]);
            }
        }

        // ---- causal mask (diagonal tiles only) ----
        if (kb >= 2 * qb) {
            const int qr = qb * 128 + wid * 16 + g;
            const int kv0 = kb * 64;
#pragma unroll
            for (int j = 0; j < 8; j++) {
                const int col = kv0 + j * 8 + t2;
#pragma unroll
                for (int qi = 0; qi < 4; qi++) {
                    const int row = qr + ((qi >> 1) << 3);
                    if (col + (qi & 1) > row) cfr[j][qi] = -1e30f;
                }
            }
        }

        // ---- online softmax (log2 domain) ----
        float mx0 = -1e30f, mx1 = -1e30f;
#pragma unroll
        for (int j = 0; j < 8; j++) {
            mx0 = fmaxf(mx0, fmaxf(cfr[j][0], cfr[j][1]));
            mx1 = fmaxf(mx1, fmaxf(cfr[j][2], cfr[j][3]));
        }
        mx0 = qred_max(mx0);
        mx1 = qred_max(mx1);
        const float mn0 = fmaxf(mrow0, mx0), mn1 = fmaxf(mrow1, mx1);
        const float al0 = exp2f(mrow0 - mn0), al1 = exp2f(mrow1 - mn1);
        mrow0 = mn0; mrow1 = mn1;
        float s0 = 0.f, s1 = 0.f;
#pragma unroll
        for (int j = 0; j < 8; j++) {
            cfr[j][0] = exp2f(cfr[j][0] - mn0);
            cfr[j][1] = exp2f(cfr[j][1] - mn0);
            cfr[j][2] = exp2f(cfr[j][2] - mn1);
            cfr[j][3] = exp2f(cfr[j][3] - mn1);
            s0 += cfr[j][0] + cfr[j][1];
            s1 += cfr[j][2] + cfr[j][3];
        }
        s0 = qred_sum(s0);
        s1 = qred_sum(s1);
        lrow0 = lrow0 * al0 + s0;
        lrow1 = lrow1 * al1 + s1;
#pragma unroll
        for (int j = 0; j < 8; j++) {
            ofr[j][0] *= al0; ofr[j][1] *= al0;
            ofr[j][2] *= al1; ofr[j][3] *= al1;
        }

        // ---- O += P V ----
#pragma unroll
        for (int kc = 0; kc < 4; kc++) {
            uint32_t ph[4], pl[4];
            packsplit(cfr[2 * kc][0],     cfr[2 * kc][1],     ph[0], pl[0]);
            packsplit(cfr[2 * kc][2],     cfr[2 * kc][3],     ph[1], pl[1]);
            packsplit(cfr[2 * kc + 1][0], cfr[2 * kc + 1][1], ph[2], pl[2]);
            packsplit(cfr[2 * kc + 1][2], cfr[2 * kc + 1][3], ph[3], pl[3]);
#pragma unroll
            for (int nc = 0; nc < 4; nc++) {
                uint32_t vh4[4];
                const uint32_t off = swz((uint32_t)((kc * 16 + lrow16) * 128 + nc * 32 + lhi));
                ldsm4t(vh4, kvb + 8192 + off);
                mma2(ofr[2 * nc],     ph, vh4[0], vh4[1]);
                mma2(ofr[2 * nc],     pl, vh4[0], vh4[1]);
                mma2(ofr[2 * nc + 1], ph, vh4[2], vh4[3]);
                mma2(ofr[2 * nc + 1], pl, vh4[2], vh4[3]);
            }
        }
    }

    // ---- epilogue: write hi/lo fp16 into [B,T,C] for proj GEMM ----
    const float inv0 = 1.f / lrow0, inv1 = 1.f / lrow1;
    const int b = bh >> 4, h = bh & 15;
    const int t0 = qb * 128 + wid * 16 + g;
#pragma unroll
    for (int j = 0; j < 8; j++) {
        const int d = j * 8 + t2;
        const size_t i0 = ((size_t)(b * T_ + t0)) * C_ + h * 64 + d;
        const size_t i1 = i0 + (size_t)8 * C_;
        uint32_t hi, lo;
        packsplit(ofr[j][0] * inv0, ofr[j][1] * inv0, hi, lo);
        *(uint32_t*)&g_ah[i0] = hi;
        *(uint32_t*)&g_al[i0] = lo;
        packsplit(ofr[j][2] * inv1, ofr[j][3] * inv1, hi, lo);
        *(uint32_t*)&g_ah[i1] = hi;
        *(uint32_t*)&g_al[i1] = lo;
    }
}

// ---------------------------------------------------------------------------
// Launch. Inputs: x, mask, W_attn, b_attn, W_proj, b_proj.
// Output: [out (B,T,C) | k (B,H,T,D) | v (B,H,T,D)] fp32.
// ---------------------------------------------------------------------------
extern "C" void kernel_launch(void* const* d_in, const int* in_sizes, int n_in,
                              void* d_out, int out_size)
{
    (void)in_sizes; (void)n_in; (void)out_size;
    const float* x      = (const float*)d_in[0];
    const float* W_attn = (const float*)d_in[2];
    const float* b_attn = (const float*)d_in[3];
    const float* W_proj = (const float*)d_in[4];
    const float* b_proj = (const float*)d_in[5];

    float* out  = (float*)d_out;
    float* kout = out + (size_t)B_ * H_ * T_ * D_;
    float* vout = kout + (size_t)B_ * H_ * T_ * D_;

    cudaFuncSetAttribute(mma_gemm<0>, cudaFuncAttributeMaxDynamicSharedMemorySize,
                         SMEM_GEMM_BYTES);
    cudaFuncSetAttribute(mma_gemm<1>, cudaFuncAttributeMaxDynamicSharedMemorySize,
                         SMEM_GEMM_BYTES);
    cudaFuncSetAttribute(attn_mma, cudaFuncAttributeMaxDynamicSharedMemorySize,
                         AT_SMEM);

    // 1) conversions
    split_x<<<1024, 256>>>(x);
    tsplit_kernel<0><<<dim3(96, 32), dim3(32, 8)>>>(W_attn);
    tsplit_kernel<1><<<dim3(32, 32), dim3(32, 8)>>>(W_proj);

    // 2) QKV GEMM + bias + scatter
    mma_gemm<0><<<dim3(24, 64), 256, SMEM_GEMM_BYTES>>>(b_attn, nullptr, kout, vout);

    // 3) causal flash attention (tensor cores) -> g_ah/g_al
    attn_mma<<<dim3(16, 64), 256, AT_SMEM>>>();

    // 4) proj GEMM
    mma_gemm<1><<<dim3(8, 64), 256, SMEM_GEMM_BYTES>>>(b_proj, out, nullptr, nullptr);
}

// round 6
// speedup vs baseline: 4.6596x; 1.0127x over previous
#include <cuda_runtime.h>
#include <cuda_fp16.h>
#include <cstdint>

// Problem constants
#define B_ 4
#define T_ 2048
#define C_ 1024
#define H_ 16
#define D_ 64
#define BT_ (B_ * T_)            // 8192
#define KDIM 1024

#define QSCALE 0.18033688011112042f   // 0.125 * log2(e)

// ---------------------------------------------------------------------------
// Scratch (device globals — no allocation allowed). All splits fp16 hi/lo.
// ---------------------------------------------------------------------------
__device__ __half g_xh[(size_t)BT_ * KDIM];    // x hi/lo
__device__ __half g_xl[(size_t)BT_ * KDIM];
__device__ __half g_wh[(size_t)3 * C_ * KDIM]; // W_attn^T hi [3072][1024]
__device__ __half g_ph[(size_t)C_ * KDIM];     // W_proj^T hi [1024][1024]
__device__ __half g_ah[(size_t)BT_ * KDIM];    // attn-out hi/lo [B,T,C]
__device__ __half g_al[(size_t)BT_ * KDIM];
// Q hi/lo, K hi, V hi in [B,H,T,D]; q pre-scaled by QSCALE
__device__ __half g_qh[(size_t)BT_ * C_];
__device__ __half g_ql[(size_t)BT_ * C_];
__device__ __half g_kh[(size_t)BT_ * C_];
__device__ __half g_vh[(size_t)BT_ * C_];

// ---------------------------------------------------------------------------
// helpers (sm_80-era PTX — legal at compute_103 base)
// ---------------------------------------------------------------------------
__device__ __forceinline__ uint32_t s2u(const void* p) {
    uint32_t a;
    asm("{ .reg .u64 t; cvta.to.shared.u64 t, %1; cvt.u32.u64 %0, t; }" : "=r"(a) : "l"(p));
    return a;
}
__device__ __forceinline__ uint32_t swz(uint32_t off) {   // SW128
    return off ^ ((off >> 3) & 0x70);
}
__device__ __forceinline__ void cp_async16(uint32_t dst, const void* src) {
    asm volatile("cp.async.cg.shared.global [%0], [%1], 16;" :: "r"(dst), "l"(src) : "memory");
}
__device__ __forceinline__ void ldsm4(uint32_t* r, uint32_t addr) {
    asm volatile("ldmatrix.sync.aligned.m8n8.x4.shared.b16 {%0,%1,%2,%3}, [%4];"
                 : "=r"(r[0]), "=r"(r[1]), "=r"(r[2]), "=r"(r[3]) : "r"(addr));
}
__device__ __forceinline__ void ldsm4t(uint32_t* r, uint32_t addr) {
    asm volatile("ldmatrix.sync.aligned.m8n8.x4.trans.shared.b16 {%0,%1,%2,%3}, [%4];"
                 : "=r"(r[0]), "=r"(r[1]), "=r"(r[2]), "=r"(r[3]) : "r"(addr));
}
__device__ __forceinline__ void mma2(float* c, const uint32_t* a, uint32_t b0, uint32_t b1) {
    asm volatile(
        "mma.sync.aligned.m16n8k16.row.col.f32.f16.f16.f32 "
        "{%0,%1,%2,%3}, {%4,%5,%6,%7}, {%8,%9}, {%0,%1,%2,%3};"
        : "+f"(c[0]), "+f"(c[1]), "+f"(c[2]), "+f"(c[3])
        : "r"(a[0]), "r"(a[1]), "r"(a[2]), "r"(a[3]), "r"(b0), "r"(b1));
}
__device__ __forceinline__ uint32_t packh2(float x, float y) {
    __half2 t; t.x = __float2half(x); t.y = __float2half(y);
    return *(uint32_t*)&t;
}
__device__ __forceinline__ void packsplit(float x, float y, uint32_t& hi, uint32_t& lo) {
    __half2 h, l;
    h.x = __float2half(x); h.y = __float2half(y);
    l.x = __float2half(x - __half2float(h.x));
    l.y = __float2half(y - __half2float(h.y));
    hi = *(uint32_t*)&h; lo = *(uint32_t*)&l;
}
__device__ __forceinline__ float qred_max(float v) {
    v = fmaxf(v, __shfl_xor_sync(~0u, v, 1));
    return fmaxf(v, __shfl_xor_sync(~0u, v, 2));
}
__device__ __forceinline__ float qred_sum(float v) {
    v += __shfl_xor_sync(~0u, v, 1);
    return v + __shfl_xor_sync(~0u, v, 2);
}

// ---------------------------------------------------------------------------
// Conversion kernels
// ---------------------------------------------------------------------------
__global__ void split_x(const float* __restrict__ s)
{
    const size_t n4 = (size_t)BT_ * KDIM / 4;
    for (size_t i = (size_t)blockIdx.x * blockDim.x + threadIdx.x; i < n4;
         i += (size_t)gridDim.x * blockDim.x) {
        float4 v = ((const float4*)s)[i];
        uint32_t h0, l0, h1, l1;
        packsplit(v.x, v.y, h0, l0);
        packsplit(v.z, v.w, h1, l1);
        ((uint32_t*)g_xh)[2 * i] = h0; ((uint32_t*)g_xh)[2 * i + 1] = h1;
        ((uint32_t*)g_xl)[2 * i] = l0; ((uint32_t*)g_xl)[2 * i + 1] = l1;
    }
}

// fp32 W [K=1024, NC] row-major -> transposed fp16 hi [NC, 1024]
template <int W>
__global__ void tsplit_kernel(const float* __restrict__ src)
{
    constexpr int NC = (W == 0) ? 3 * C_ : C_;
    __half* dh = (W == 0) ? g_wh : g_ph;
    __shared__ float tile[32][33];
    const int x = blockIdx.x * 32 + threadIdx.x;
    const int y0 = blockIdx.y * 32;
#pragma unroll
    for (int j = 0; j < 32; j += 8)
        tile[threadIdx.y + j][threadIdx.x] = src[(size_t)(y0 + threadIdx.y + j) * NC + x];
    __syncthreads();
    const int ox = y0 + threadIdx.x;
    const int oyb = blockIdx.x * 32;
#pragma unroll
    for (int j = 0; j < 32; j += 8)
        dh[(size_t)(oyb + threadIdx.y + j) * KDIM + ox] =
            __float2half(tile[threadIdx.x][threadIdx.y + j]);
}

// ---------------------------------------------------------------------------
// fp16x2 GEMM via mma.sync: D = A x B^T, A split hi/lo, B hi only.
// CTA tile 128x64, warp tile 32x32 (8 warps), K_chunk=64, 2-stage cp.async,
// 2 CTAs/SM. Stage = [Ah 16K][Al 16K][Bh 8K] = 40KB.
// ---------------------------------------------------------------------------
#define SM_STAGE 40960
#define SMEM_GEMM_BYTES 81920    // 2 stages

template <int MODE>
__global__ __launch_bounds__(256, 2)
void mma_gemm(const float* __restrict__ bias,
              float* __restrict__ o0, float* __restrict__ o1, float* __restrict__ o2)
{
    extern __shared__ __align__(1024) char smem[];
    const uint32_t sm = s2u(smem);
    const int tid = threadIdx.x;
    const int wid = tid >> 5;
    const int lid = tid & 31;
    const int n0 = blockIdx.x * 64;
    const int m0 = blockIdx.y * 128;

    const __half* Ahp = (MODE == 0) ? g_xh : g_ah;
    const __half* Alp = (MODE == 0) ? g_xl : g_al;
    const __half* Bhp = (MODE == 0) ? g_wh : g_ph;

    // copy plan: 2560 x 16B per stage, 10 per thread (recomputed, not cached)
    auto issue_loads = [&](int c, int s) {
        const uint32_t sb = sm + (uint32_t)s * SM_STAGE;
#pragma unroll
        for (int r = 0; r < 10; r++) {
            const int id = tid + r * 256;
            const int c16 = id & 7;
            const uint32_t koff = (uint32_t)(c16 * 16);
            if (id < 1024) {
                const int row = id >> 3;
                cp_async16(sb + swz((uint32_t)(row * 128) + koff),
                           Ahp + (size_t)(m0 + row) * KDIM + c * 64 + c16 * 8);
            } else if (id < 2048) {
                const int row = (id >> 3) & 127;
                cp_async16(sb + 16384 + swz((uint32_t)(row * 128) + koff),
                           Alp + (size_t)(m0 + row) * KDIM + c * 64 + c16 * 8);
            } else if (id < 2560) {
                const int row = (id >> 3) & 63;
                cp_async16(sb + 32768 + swz((uint32_t)(row * 128) + koff),
                           Bhp + (size_t)(n0 + row) * KDIM + c * 64 + c16 * 8);
            }
        }
        asm volatile("cp.async.commit_group;" ::: "memory");
    };

    const int wm = (wid & 3) * 32;       // warp M origin
    const int wn = (wid >> 2) * 32;      // warp N origin
    const int g = lid >> 2;
    const int tig = lid & 3;
    const int aRow = lid & 15;
    const int aKb = (lid >> 4) * 16;
    const int bRow = ((lid >> 4) & 1) * 8 + (lid & 7);
    const int bKb = ((lid >> 3) & 1) * 16;

    float Cr[2][4][4];
#pragma unroll
    for (int mi = 0; mi < 2; mi++)
#pragma unroll
        for (int j = 0; j < 4; j++)
#pragma unroll
            for (int qi = 0; qi < 4; qi++) Cr[mi][j][qi] = 0.f;

    issue_loads(0, 0);
    issue_loads(1, 1);

    for (int c = 0; c < 16; c++) {
        const int s = c & 1;
        if (c < 15) asm volatile("cp.async.wait_group 1;" ::: "memory");
        else        asm volatile("cp.async.wait_group 0;" ::: "memory");
        __syncthreads();

        const uint32_t sb = sm + (uint32_t)s * SM_STAGE;
        const uint32_t tAh = sb, tAl = sb + 16384, tBh = sb + 32768;

#pragma unroll
        for (int ks = 0; ks < 4; ks++) {
            const int kb = ks * 32;
            uint32_t ah[2][4], al[2][4], bh[2][4];
#pragma unroll
            for (int mi = 0; mi < 2; mi++) {
                const uint32_t off = swz((uint32_t)((wm + mi * 16 + aRow) * 128 + kb + aKb));
                ldsm4(ah[mi], tAh + off);
                ldsm4(al[mi], tAl + off);
            }
#pragma unroll
            for (int jp = 0; jp < 2; jp++) {
                const uint32_t off = swz((uint32_t)((wn + jp * 16 + bRow) * 128 + kb + bKb));
                ldsm4(bh[jp], tBh + off);
            }
#pragma unroll
            for (int mi = 0; mi < 2; mi++)
#pragma unroll
                for (int j = 0; j < 4; j++) {
                    const int jp = j >> 1, o = (j & 1) * 2;
                    mma2(Cr[mi][j], ah[mi], bh[jp][o], bh[jp][o + 1]);
                    mma2(Cr[mi][j], al[mi], bh[jp][o], bh[jp][o + 1]);
                }
        }
        __syncthreads();              // all reads of stage s done
        if (c + 2 < 16) issue_loads(c + 2, s);
    }

    // ---- epilogue ----
#pragma unroll
    for (int mi = 0; mi < 2; mi++)
#pragma unroll
        for (int j = 0; j < 4; j++) {
            const int col = n0 + wn + j * 8 + tig * 2;
            const float2 bb = *(const float2*)(bias + col);
#pragma unroll
            for (int half = 0; half < 2; half++) {
                const int row = m0 + wm + mi * 16 + g + half * 8;
                float2 v;
                v.x = Cr[mi][j][half * 2 + 0] + bb.x;
                v.y = Cr[mi][j][half * 2 + 1] + bb.y;
                if (MODE == 0) {
                    const int seg = col >> 10;
                    const int c0 = col & 1023;
                    const int h = c0 >> 6;
                    const int dd = c0 & 63;
                    const int b = row >> 11;
                    const int t = row & (T_ - 1);
                    const size_t idx = ((size_t)(b * H_ + h) * T_ + t) * D_ + dd;
                    if (seg == 0) {
                        uint32_t hi, lo;
                        packsplit(v.x * QSCALE, v.y * QSCALE, hi, lo);
                        *(uint32_t*)&g_qh[idx] = hi;
                        *(uint32_t*)&g_ql[idx] = lo;
                    } else if (seg == 1) {
                        *(float2*)&o1[idx] = v;
                        *(uint32_t*)&g_kh[idx] = packh2(v.x, v.y);
                    } else {
                        *(float2*)&o2[idx] = v;
                        *(uint32_t*)&g_vh[idx] = packh2(v.x, v.y);
                    }
                } else {
                    *(float2*)&o0[(size_t)row * C_ + col] = v;
                }
            }
        }
}

// ---------------------------------------------------------------------------
// Flash attention via mma.sync fp16x2; now 2-stage KV + 2 CTAs/SM.
// CTA: 128 q-rows; kv tiles 64; 8 warps x 16 rows.
// smem: Qh/Ql 16KB @0/16384; stage s @32768+s*16384: [Kh 8KB][Vh 8KB]
// ---------------------------------------------------------------------------
#define AT_SMEM 65536            // Q 32K + 2 stages x 16K

__global__ __launch_bounds__(256, 2)
void attn_mma()
{
    extern __shared__ __align__(1024) char smem[];
    const uint32_t sm = s2u(smem);
    const int tid = threadIdx.x;
    const int wid = tid >> 5;
    const int lid = tid & 31;
    const int qb = 15 - blockIdx.x;          // heavy CTAs first
    const int bh = blockIdx.y;
    const size_t base_qkv = (size_t)bh * T_ * D_;
    const int nt = 2 * qb + 2;

    // Q loads (folded into group 0)
#pragma unroll
    for (int r = 0; r < 8; r++) {
        const int id = tid + r * 256;
        const int bsel = id >> 10;
        const int row = (id >> 3) & 127;
        const int c16 = id & 7;
        const uint32_t dst = sm + bsel * 16384 + swz((uint32_t)(row * 128 + c16 * 16));
        const __half* src = (bsel ? g_ql : g_qh) + base_qkv
                            + (size_t)(qb * 128 + row) * D_ + c16 * 8;
        cp_async16(dst, src);
    }
    auto issue_kv = [&](int kt, int s) {
        const uint32_t sb = sm + 32768 + (uint32_t)s * 16384;
#pragma unroll
        for (int r = 0; r < 4; r++) {
            const int id = tid + r * 256;
            const int bsel = id >> 9;        // 0 Kh 1 Vh
            const int row = (id >> 3) & 63;
            const int c16 = id & 7;
            const uint32_t dst = sb + bsel * 8192 + swz((uint32_t)(row * 128 + c16 * 16));
            const __half* src = (bsel ? g_vh : g_kh) + base_qkv
                                + (size_t)(kt * 64 + row) * D_ + c16 * 8;
            cp_async16(dst, src);
        }
        asm volatile("cp.async.commit_group;" ::: "memory");
    };
    issue_kv(0, 0);
    issue_kv(1, 1);

    const int g = lid >> 2;
    const int t2 = (lid & 3) * 2;
    const int lrow16 = lid & 15;
    const int lhi = (lid >> 4) * 16;

    uint32_t qh[4][4], ql[4][4];
    float cfr[8][4], ofr[8][4];
    float mrow0 = -1e30f, mrow1 = -1e30f, lrow0 = 0.f, lrow1 = 0.f;
#pragma unroll
    for (int j = 0; j < 8; j++)
#pragma unroll
        for (int qi = 0; qi < 4; qi++) ofr[j][qi] = 0.f;

    for (int kb = 0; kb < nt; kb++) {
        const int s = kb & 1;
        if (kb + 1 < nt) asm volatile("cp.async.wait_group 1;" ::: "memory");
        else             asm volatile("cp.async.wait_group 0;" ::: "memory");
        __syncthreads();
        if (kb == 0) {
#pragma unroll
            for (int kc = 0; kc < 4; kc++) {
                const uint32_t off = swz((uint32_t)((wid * 16 + lrow16) * 128 + kc * 32 + lhi));
                ldsm4(qh[kc], sm + off);
                ldsm4(ql[kc], sm + 16384 + off);
            }
        }
        const uint32_t kvb = sm + 32768 + (uint32_t)s * 16384;

        // ---- S = Q K^T ----
#pragma unroll
        for (int j = 0; j < 8; j++)
#pragma unroll
            for (int qi = 0; qi < 4; qi++) cfr[j][qi] = 0.f;
#pragma unroll
        for (int kc = 0; kc < 4; kc++) {
            uint32_t kh4[4][4];
#pragma unroll
            for (int jp = 0; jp < 4; jp++) {
                const uint32_t off = swz((uint32_t)((jp * 16 + lrow16) * 128 + kc * 32 + lhi));
                ldsm4(kh4[jp], kvb + off);
            }
#pragma unroll
            for (int jp = 0; jp < 4; jp++) {
                mma2(cfr[2 * jp],     qh[kc], kh4[jp][0], kh4[jp][2]);
                mma2(cfr[2 * jp],     ql[kc], kh4[jp][0], kh4[jp][2]);
                mma2(cfr[2 * jp + 1], qh[kc], kh4[jp][1], kh4[jp][3]);
                mma2(cfr[2 * jp + 1], ql[kc], kh4[jp][1], kh4[jp][3]);
            }
        }

        // ---- causal mask (diagonal tiles only) ----
        if (kb >= 2 * qb) {
            const int qr = qb * 128 + wid * 16 + g;
            const int kv0 = kb * 64;
#pragma unroll
            for (int j = 0; j < 8; j++) {
                const int col = kv0 + j * 8 + t2;
#pragma unroll
                for (int qi = 0; qi < 4; qi++) {
                    const int row = qr + ((qi >> 1) << 3);
                    if (col + (qi & 1) > row) cfr[j][qi] = -1e30f;
                }
            }
        }

        // ---- online softmax (log2 domain) ----
        float mx0 = -1e30f, mx1 = -1e30f;
#pragma unroll
        for (int j = 0; j < 8; j++) {
            mx0 = fmaxf(mx0, fmaxf(cfr[j][0], cfr[j][1]));
            mx1 = fmaxf(mx1, fmaxf(cfr[j][2], cfr[j][3]));
        }
        mx0 = qred_max(mx0);
        mx1 = qred_max(mx1);
        const float mn0 = fmaxf(mrow0, mx0), mn1 = fmaxf(mrow1, mx1);
        const float al0 = exp2f(mrow0 - mn0), al1 = exp2f(mrow1 - mn1);
        mrow0 = mn0; mrow1 = mn1;
        float s0 = 0.f, s1 = 0.f;
#pragma unroll
        for (int j = 0; j < 8; j++) {
            cfr[j][0] = exp2f(cfr[j][0] - mn0);
            cfr[j][1] = exp2f(cfr[j][1] - mn0);
            cfr[j][2] = exp2f(cfr[j][2] - mn1);
            cfr[j][3] = exp2f(cfr[j][3] - mn1);
            s0 += cfr[j][0] + cfr[j][1];
            s1 += cfr[j][2] + cfr[j][3];
        }
        s0 = qred_sum(s0);
        s1 = qred_sum(s1);
        lrow0 = lrow0 * al0 + s0;
        lrow1 = lrow1 * al1 + s1;
#pragma unroll
        for (int j = 0; j < 8; j++) {
            ofr[j][0] *= al0; ofr[j][1] *= al0;
            ofr[j][2] *= al1; ofr[j][3] *= al1;
        }

        // ---- O += P V ----
#pragma unroll
        for (int kc = 0; kc < 4; kc++) {
            uint32_t ph[4], pl[4];
            packsplit(cfr[2 * kc][0],     cfr[2 * kc][1],     ph[0], pl[0]);
            packsplit(cfr[2 * kc][2],     cfr[2 * kc][3],     ph[1], pl[1]);
            packsplit(cfr[2 * kc + 1][0], cfr[2 * kc + 1][1], ph[2], pl[2]);
            packsplit(cfr[2 * kc + 1][2], cfr[2 * kc + 1][3], ph[3], pl[3]);
#pragma unroll
            for (int nc = 0; nc < 4; nc++) {
                uint32_t vh4[4];
                const uint32_t off = swz((uint32_t)((kc * 16 + lrow16) * 128 + nc * 32 + lhi));
                ldsm4t(vh4, kvb + 8192 + off);
                mma2(ofr[2 * nc],     ph, vh4[0], vh4[1]);
                mma2(ofr[2 * nc],     pl, vh4[0], vh4[1]);
                mma2(ofr[2 * nc + 1], ph, vh4[2], vh4[3]);
                mma2(ofr[2 * nc + 1], pl, vh4[2], vh4[3]);
            }
        }
        __syncthreads();              // stage s fully consumed
        if (kb + 2 < nt) issue_kv(kb + 2, s);
    }

    // ---- epilogue: write hi/lo fp16 into [B,T,C] for proj GEMM ----
    const float inv0 = 1.f / lrow0, inv1 = 1.f / lrow1;
    const int b = bh >> 4, h = bh & 15;
    const int t0 = qb * 128 + wid * 16 + g;
#pragma unroll
    for (int j = 0; j < 8; j++) {
        const int d = j * 8 + t2;
        const size_t i0 = ((size_t)(b * T_ + t0)) * C_ + h * 64 + d;
        const size_t i1 = i0 + (size_t)8 * C_;
        uint32_t hi, lo;
        packsplit(ofr[j][0] * inv0, ofr[j][1] * inv0, hi, lo);
        *(uint32_t*)&g_ah[i0] = hi;
        *(uint32_t*)&g_al[i0] = lo;
        packsplit(ofr[j][2] * inv1, ofr[j][3] * inv1, hi, lo);
        *(uint32_t*)&g_ah[i1] = hi;
        *(uint32_t*)&g_al[i1] = lo;
    }
}

// ---------------------------------------------------------------------------
// Launch. Inputs: x, mask, W_attn, b_attn, W_proj, b_proj.
// Output: [out (B,T,C) | k (B,H,T,D) | v (B,H,T,D)] fp32.
// ---------------------------------------------------------------------------
extern "C" void kernel_launch(void* const* d_in, const int* in_sizes, int n_in,
                              void* d_out, int out_size)
{
    (void)in_sizes; (void)n_in; (void)out_size;
    const float* x      = (const float*)d_in[0];
    const float* W_attn = (const float*)d_in[2];
    const float* b_attn = (const float*)d_in[3];
    const float* W_proj = (const float*)d_in[4];
    const float* b_proj = (const float*)d_in[5];

    float* out  = (float*)d_out;
    float* kout = out + (size_t)B_ * H_ * T_ * D_;
    float* vout = kout + (size_t)B_ * H_ * T_ * D_;

    cudaFuncSetAttribute(mma_gemm<0>, cudaFuncAttributeMaxDynamicSharedMemorySize,
                         SMEM_GEMM_BYTES);
    cudaFuncSetAttribute(mma_gemm<1>, cudaFuncAttributeMaxDynamicSharedMemorySize,
                         SMEM_GEMM_BYTES);
    cudaFuncSetAttribute(attn_mma, cudaFuncAttributeMaxDynamicSharedMemorySize,
                         AT_SMEM);

    // 1) conversions
    split_x<<<1024, 256>>>(x);
    tsplit_kernel<0><<<dim3(96, 32), dim3(32, 8)>>>(W_attn);
    tsplit_kernel<1><<<dim3(32, 32), dim3(32, 8)>>>(W_proj);

    // 2) QKV GEMM + bias + scatter (N tile 64 -> grid x = 3072/64 = 48)
    mma_gemm<0><<<dim3(48, 64), 256, SMEM_GEMM_BYTES>>>(b_attn, nullptr, kout, vout);

    // 3) causal flash attention (tensor cores) -> g_ah/g_al
    attn_mma<<<dim3(16, 64), 256, AT_SMEM>>>();

    // 4) proj GEMM (grid x = 1024/64 = 16)
    mma_gemm<1><<<dim3(16, 64), 256, SMEM_GEMM_BYTES>>>(b_proj, out, nullptr, nullptr);
}

// round 7
// speedup vs baseline: 4.7454x; 1.0184x over previous
#include <cuda_runtime.h>
#include <cuda_fp16.h>
#include <cstdint>

// Problem constants
#define B_ 4
#define T_ 2048
#define C_ 1024
#define H_ 16
#define D_ 64
#define BT_ (B_ * T_)            // 8192
#define KDIM 1024

#define QSCALE 0.18033688011112042f   // 0.125 * log2(e)

// ---------------------------------------------------------------------------
// Scratch (device globals — no allocation allowed). All splits fp16 hi/lo.
// ---------------------------------------------------------------------------
__device__ __half g_xh[(size_t)BT_ * KDIM];    // x hi/lo
__device__ __half g_xl[(size_t)BT_ * KDIM];
__device__ __half g_wh[(size_t)3 * C_ * KDIM]; // W_attn^T hi [3072][1024]
__device__ __half g_ph[(size_t)C_ * KDIM];     // W_proj^T hi [1024][1024]
__device__ __half g_ah[(size_t)BT_ * KDIM];    // attn-out hi/lo [B,T,C]
__device__ __half g_al[(size_t)BT_ * KDIM];
// Q hi/lo, K hi, V hi in [B,H,T,D]; q pre-scaled by QSCALE
__device__ __half g_qh[(size_t)BT_ * C_];
__device__ __half g_ql[(size_t)BT_ * C_];
__device__ __half g_kh[(size_t)BT_ * C_];
__device__ __half g_vh[(size_t)BT_ * C_];

// ---------------------------------------------------------------------------
// helpers (sm_80-era PTX — legal at compute_103 base)
// ---------------------------------------------------------------------------
__device__ __forceinline__ uint32_t s2u(const void* p) {
    uint32_t a;
    asm("{ .reg .u64 t; cvta.to.shared.u64 t, %1; cvt.u32.u64 %0, t; }" : "=r"(a) : "l"(p));
    return a;
}
__device__ __forceinline__ uint32_t swz(uint32_t off) {   // SW128
    return off ^ ((off >> 3) & 0x70);
}
__device__ __forceinline__ void cp_async16(uint32_t dst, const void* src) {
    asm volatile("cp.async.cg.shared.global [%0], [%1], 16;" :: "r"(dst), "l"(src) : "memory");
}
__device__ __forceinline__ void ldsm4(uint32_t* r, uint32_t addr) {
    asm volatile("ldmatrix.sync.aligned.m8n8.x4.shared.b16 {%0,%1,%2,%3}, [%4];"
                 : "=r"(r[0]), "=r"(r[1]), "=r"(r[2]), "=r"(r[3]) : "r"(addr));
}
__device__ __forceinline__ void ldsm4t(uint32_t* r, uint32_t addr) {
    asm volatile("ldmatrix.sync.aligned.m8n8.x4.trans.shared.b16 {%0,%1,%2,%3}, [%4];"
                 : "=r"(r[0]), "=r"(r[1]), "=r"(r[2]), "=r"(r[3]) : "r"(addr));
}
__device__ __forceinline__ void mma2(float* c, const uint32_t* a, uint32_t b0, uint32_t b1) {
    asm volatile(
        "mma.sync.aligned.m16n8k16.row.col.f32.f16.f16.f32 "
        "{%0,%1,%2,%3}, {%4,%5,%6,%7}, {%8,%9}, {%0,%1,%2,%3};"
        : "+f"(c[0]), "+f"(c[1]), "+f"(c[2]), "+f"(c[3])
        : "r"(a[0]), "r"(a[1]), "r"(a[2]), "r"(a[3]), "r"(b0), "r"(b1));
}
__device__ __forceinline__ uint32_t packh2(float x, float y) {
    __half2 t; t.x = __float2half(x); t.y = __float2half(y);
    return *(uint32_t*)&t;
}
__device__ __forceinline__ void packsplit(float x, float y, uint32_t& hi, uint32_t& lo) {
    __half2 h, l;
    h.x = __float2half(x); h.y = __float2half(y);
    l.x = __float2half(x - __half2float(h.x));
    l.y = __float2half(y - __half2float(h.y));
    hi = *(uint32_t*)&h; lo = *(uint32_t*)&l;
}
__device__ __forceinline__ float qred_max(float v) {
    v = fmaxf(v, __shfl_xor_sync(~0u, v, 1));
    return fmaxf(v, __shfl_xor_sync(~0u, v, 2));
}
__device__ __forceinline__ float qred_sum(float v) {
    v += __shfl_xor_sync(~0u, v, 1);
    return v + __shfl_xor_sync(~0u, v, 2);
}

// ---------------------------------------------------------------------------
// Conversion kernels
// ---------------------------------------------------------------------------
__global__ void split_x(const float* __restrict__ s)
{
    const size_t n4 = (size_t)BT_ * KDIM / 4;
    for (size_t i = (size_t)blockIdx.x * blockDim.x + threadIdx.x; i < n4;
         i += (size_t)gridDim.x * blockDim.x) {
        float4 v = ((const float4*)s)[i];
        uint32_t h0, l0, h1, l1;
        packsplit(v.x, v.y, h0, l0);
        packsplit(v.z, v.w, h1, l1);
        ((uint32_t*)g_xh)[2 * i] = h0; ((uint32_t*)g_xh)[2 * i + 1] = h1;
        ((uint32_t*)g_xl)[2 * i] = l0; ((uint32_t*)g_xl)[2 * i + 1] = l1;
    }
}

// fp32 W [K=1024, NC] row-major -> transposed fp16 hi [NC, 1024]
template <int W>
__global__ void tsplit_kernel(const float* __restrict__ src)
{
    constexpr int NC = (W == 0) ? 3 * C_ : C_;
    __half* dh = (W == 0) ? g_wh : g_ph;
    __shared__ float tile[32][33];
    const int x = blockIdx.x * 32 + threadIdx.x;
    const int y0 = blockIdx.y * 32;
#pragma unroll
    for (int j = 0; j < 32; j += 8)
        tile[threadIdx.y + j][threadIdx.x] = src[(size_t)(y0 + threadIdx.y + j) * NC + x];
    __syncthreads();
    const int ox = y0 + threadIdx.x;
    const int oyb = blockIdx.x * 32;
#pragma unroll
    for (int j = 0; j < 32; j += 8)
        dh[(size_t)(oyb + threadIdx.y + j) * KDIM + ox] =
            __float2half(tile[threadIdx.x][threadIdx.y + j]);
}

// ---------------------------------------------------------------------------
// fp16x2 GEMM via mma.sync: D = A x B^T, A split hi/lo, B hi only.
// CTA tile 128x64, warp tile 32x32 (8 warps), K_chunk=64, 2-stage cp.async,
// 2 CTAs/SM. Stage = [Ah 16K][Al 16K][Bh 8K] = 40KB.
// Chunk schedule: F0 F1 M0 F2 M1 F3 M2 | sync | issue | M3 (frag dbl-buffer)
// ---------------------------------------------------------------------------
#define SM_STAGE 40960
#define SMEM_GEMM_BYTES 81920    // 2 stages

template <int MODE>
__global__ __launch_bounds__(256, 2)
void mma_gemm(const float* __restrict__ bias,
              float* __restrict__ o0, float* __restrict__ o1, float* __restrict__ o2)
{
    extern __shared__ __align__(1024) char smem[];
    const uint32_t sm = s2u(smem);
    const int tid = threadIdx.x;
    const int wid = tid >> 5;
    const int lid = tid & 31;
    const int n0 = blockIdx.x * 64;
    const int m0 = blockIdx.y * 128;

    const __half* Ahp = (MODE == 0) ? g_xh : g_ah;
    const __half* Alp = (MODE == 0) ? g_xl : g_al;
    const __half* Bhp = (MODE == 0) ? g_wh : g_ph;

    auto issue_loads = [&](int c, int s) {
        const uint32_t sb = sm + (uint32_t)s * SM_STAGE;
#pragma unroll
        for (int r = 0; r < 10; r++) {
            const int id = tid + r * 256;
            const int c16 = id & 7;
            const uint32_t koff = (uint32_t)(c16 * 16);
            if (id < 1024) {
                const int row = id >> 3;
                cp_async16(sb + swz((uint32_t)(row * 128) + koff),
                           Ahp + (size_t)(m0 + row) * KDIM + c * 64 + c16 * 8);
            } else if (id < 2048) {
                const int row = (id >> 3) & 127;
                cp_async16(sb + 16384 + swz((uint32_t)(row * 128) + koff),
                           Alp + (size_t)(m0 + row) * KDIM + c * 64 + c16 * 8);
            } else if (id < 2560) {
                const int row = (id >> 3) & 63;
                cp_async16(sb + 32768 + swz((uint32_t)(row * 128) + koff),
                           Bhp + (size_t)(n0 + row) * KDIM + c * 64 + c16 * 8);
            }
        }
        asm volatile("cp.async.commit_group;" ::: "memory");
    };

    const int wm = (wid & 3) * 32;       // warp M origin
    const int wn = (wid >> 2) * 32;      // warp N origin
    const int g = lid >> 2;
    const int tig = lid & 3;
    const int aRow = lid & 15;
    const int aKb = (lid >> 4) * 16;
    const int bRow = ((lid >> 4) & 1) * 8 + (lid & 7);
    const int bKb = ((lid >> 3) & 1) * 16;

    float Cr[2][4][4];
#pragma unroll
    for (int mi = 0; mi < 2; mi++)
#pragma unroll
        for (int j = 0; j < 4; j++)
#pragma unroll
            for (int qi = 0; qi < 4; qi++) Cr[mi][j][qi] = 0.f;

    uint32_t ah[2][2][4], al[2][2][4], bhf[2][2][4];  // [buf][mi/jp][frag]

    issue_loads(0, 0);
    issue_loads(1, 1);

    for (int c = 0; c < 16; c++) {
        const int s = c & 1;
        if (c < 15) asm volatile("cp.async.wait_group 1;" ::: "memory");
        else        asm volatile("cp.async.wait_group 0;" ::: "memory");
        __syncthreads();

        const uint32_t sb = sm + (uint32_t)s * SM_STAGE;
        const uint32_t tAh = sb, tAl = sb + 16384, tBh = sb + 32768;

        auto F = [&](int ks) {
            const int bp = ks & 1;
            const int kb = ks * 32;
#pragma unroll
            for (int mi = 0; mi < 2; mi++) {
                const uint32_t off = swz((uint32_t)((wm + mi * 16 + aRow) * 128 + kb + aKb));
                ldsm4(ah[bp][mi], tAh + off);
                ldsm4(al[bp][mi], tAl + off);
            }
#pragma unroll
            for (int jp = 0; jp < 2; jp++) {
                const uint32_t off = swz((uint32_t)((wn + jp * 16 + bRow) * 128 + kb + bKb));
                ldsm4(bhf[bp][jp], tBh + off);
            }
        };
        auto M = [&](int ks) {
            const int bp = ks & 1;
#pragma unroll
            for (int mi = 0; mi < 2; mi++)
#pragma unroll
                for (int j = 0; j < 4; j++) {
                    const int jp = j >> 1, o = (j & 1) * 2;
                    mma2(Cr[mi][j], ah[bp][mi], bhf[bp][jp][o], bhf[bp][jp][o + 1]);
                    mma2(Cr[mi][j], al[bp][mi], bhf[bp][jp][o], bhf[bp][jp][o + 1]);
                }
        };

        F(0); F(1);
        M(0); F(2);
        M(1); F(3);
        M(2);
        __syncthreads();              // all smem reads of stage s done
        if (c + 2 < 16) issue_loads(c + 2, s);
        M(3);
    }

    // ---- epilogue ----
#pragma unroll
    for (int mi = 0; mi < 2; mi++)
#pragma unroll
        for (int j = 0; j < 4; j++) {
            const int col = n0 + wn + j * 8 + tig * 2;
            const float2 bb = *(const float2*)(bias + col);
#pragma unroll
            for (int half = 0; half < 2; half++) {
                const int row = m0 + wm + mi * 16 + g + half * 8;
                float2 v;
                v.x = Cr[mi][j][half * 2 + 0] + bb.x;
                v.y = Cr[mi][j][half * 2 + 1] + bb.y;
                if (MODE == 0) {
                    const int seg = col >> 10;
                    const int c0 = col & 1023;
                    const int h = c0 >> 6;
                    const int dd = c0 & 63;
                    const int b = row >> 11;
                    const int t = row & (T_ - 1);
                    const size_t idx = ((size_t)(b * H_ + h) * T_ + t) * D_ + dd;
                    if (seg == 0) {
                        uint32_t hi, lo;
                        packsplit(v.x * QSCALE, v.y * QSCALE, hi, lo);
                        *(uint32_t*)&g_qh[idx] = hi;
                        *(uint32_t*)&g_ql[idx] = lo;
                    } else if (seg == 1) {
                        *(float2*)&o1[idx] = v;
                        *(uint32_t*)&g_kh[idx] = packh2(v.x, v.y);
                    } else {
                        *(float2*)&o2[idx] = v;
                        *(uint32_t*)&g_vh[idx] = packh2(v.x, v.y);
                    }
                } else {
                    *(float2*)&o0[(size_t)row * C_ + col] = v;
                }
            }
        }
}

// ---------------------------------------------------------------------------
// Flash attention via mma.sync fp16x2; 3-stage KV (single sync per tile),
// 2 CTAs/SM, pipelined K/V fragment loads.
// CTA: 128 q-rows; kv tiles 64; 8 warps x 16 rows.
// smem: Qh/Ql 16KB @0/16384; stage s @32768+s*16384: [Kh 8KB][Vh 8KB]
// ---------------------------------------------------------------------------
#define AT_SMEM 81920            // Q 32K + 3 stages x 16K

__global__ __launch_bounds__(256, 2)
void attn_mma()
{
    extern __shared__ __align__(1024) char smem[];
    const uint32_t sm = s2u(smem);
    const int tid = threadIdx.x;
    const int wid = tid >> 5;
    const int lid = tid & 31;
    const int qb = 15 - blockIdx.x;          // heavy CTAs first
    const int bh = blockIdx.y;
    const size_t base_qkv = (size_t)bh * T_ * D_;
    const int nt = 2 * qb + 2;

    // Q loads (folded into group 0)
#pragma unroll
    for (int r = 0; r < 8; r++) {
        const int id = tid + r * 256;
        const int bsel = id >> 10;
        const int row = (id >> 3) & 127;
        const int c16 = id & 7;
        const uint32_t dst = sm + bsel * 16384 + swz((uint32_t)(row * 128 + c16 * 16));
        const __half* src = (bsel ? g_ql : g_qh) + base_qkv
                            + (size_t)(qb * 128 + row) * D_ + c16 * 8;
        cp_async16(dst, src);
    }
    auto issue_kv = [&](int kt, int s) {
        const uint32_t sb = sm + 32768 + (uint32_t)s * 16384;
#pragma unroll
        for (int r = 0; r < 4; r++) {
            const int id = tid + r * 256;
            const int bsel = id >> 9;        // 0 Kh 1 Vh
            const int row = (id >> 3) & 63;
            const int c16 = id & 7;
            const uint32_t dst = sb + bsel * 8192 + swz((uint32_t)(row * 128 + c16 * 16));
            const __half* src = (bsel ? g_vh : g_kh) + base_qkv
                                + (size_t)(kt * 64 + row) * D_ + c16 * 8;
            cp_async16(dst, src);
        }
        asm volatile("cp.async.commit_group;" ::: "memory");
    };
    issue_kv(0, 0);
    issue_kv(1, 1);

    const int g = lid >> 2;
    const int t2 = (lid & 3) * 2;
    const int lrow16 = lid & 15;
    const int lhi = (lid >> 4) * 16;

    uint32_t qh[4][4], ql[4][4];
    float cfr[8][4], ofr[8][4];
    float mrow0 = -1e30f, mrow1 = -1e30f, lrow0 = 0.f, lrow1 = 0.f;
#pragma unroll
    for (int j = 0; j < 8; j++)
#pragma unroll
        for (int qi = 0; qi < 4; qi++) ofr[j][qi] = 0.f;

    for (int kb = 0; kb < nt; kb++) {
        const int s = kb % 3;
        if (kb + 1 < nt) asm volatile("cp.async.wait_group 1;" ::: "memory");
        else             asm volatile("cp.async.wait_group 0;" ::: "memory");
        __syncthreads();
        // stage (kb+2)%3 == (kb-1)%3; its reads finished before this sync
        if (kb + 2 < nt) issue_kv(kb + 2, (kb + 2) % 3);
        if (kb == 0) {
#pragma unroll
            for (int kc = 0; kc < 4; kc++) {
                const uint32_t off = swz((uint32_t)((wid * 16 + lrow16) * 128 + kc * 32 + lhi));
                ldsm4(qh[kc], sm + off);
                ldsm4(ql[kc], sm + 16384 + off);
            }
        }
        const uint32_t kvb = sm + 32768 + (uint32_t)s * 16384;

        // ---- S = Q K^T (pipelined K frags, 2 buffers) ----
#pragma unroll
        for (int j = 0; j < 8; j++)
#pragma unroll
            for (int qi = 0; qi < 4; qi++) cfr[j][qi] = 0.f;
#pragma unroll
        for (int kc = 0; kc < 4; kc++) {
            uint32_t khb[2][4];
            auto LK = [&](int jp, int bp) {
                const uint32_t off = swz((uint32_t)((jp * 16 + lrow16) * 128 + kc * 32 + lhi));
                ldsm4(khb[bp], kvb + off);
            };
            auto MS = [&](int jp, int bp) {
                mma2(cfr[2 * jp],     qh[kc], khb[bp][0], khb[bp][2]);
                mma2(cfr[2 * jp],     ql[kc], khb[bp][0], khb[bp][2]);
                mma2(cfr[2 * jp + 1], qh[kc], khb[bp][1], khb[bp][3]);
                mma2(cfr[2 * jp + 1], ql[kc], khb[bp][1], khb[bp][3]);
            };
            LK(0, 0); LK(1, 1);
            MS(0, 0); LK(2, 0);
            MS(1, 1); LK(3, 1);
            MS(2, 0);
            MS(3, 1);
        }

        // ---- causal mask (diagonal tiles only) ----
        if (kb >= 2 * qb) {
            const int qr = qb * 128 + wid * 16 + g;
            const int kv0 = kb * 64;
#pragma unroll
            for (int j = 0; j < 8; j++) {
                const int col = kv0 + j * 8 + t2;
#pragma unroll
                for (int qi = 0; qi < 4; qi++) {
                    const int row = qr + ((qi >> 1) << 3);
                    if (col + (qi & 1) > row) cfr[j][qi] = -1e30f;
                }
            }
        }

        // ---- online softmax (log2 domain) ----
        float mx0 = -1e30f, mx1 = -1e30f;
#pragma unroll
        for (int j = 0; j < 8; j++) {
            mx0 = fmaxf(mx0, fmaxf(cfr[j][0], cfr[j][1]));
            mx1 = fmaxf(mx1, fmaxf(cfr[j][2], cfr[j][3]));
        }
        mx0 = qred_max(mx0);
        mx1 = qred_max(mx1);
        const float mn0 = fmaxf(mrow0, mx0), mn1 = fmaxf(mrow1, mx1);
        const float al0 = exp2f(mrow0 - mn0), al1 = exp2f(mrow1 - mn1);
        mrow0 = mn0; mrow1 = mn1;
        float s0 = 0.f, s1 = 0.f;
#pragma unroll
        for (int j = 0; j < 8; j++) {
            cfr[j][0] = exp2f(cfr[j][0] - mn0);
            cfr[j][1] = exp2f(cfr[j][1] - mn0);
            cfr[j][2] = exp2f(cfr[j][2] - mn1);
            cfr[j][3] = exp2f(cfr[j][3] - mn1);
            s0 += cfr[j][0] + cfr[j][1];
            s1 += cfr[j][2] + cfr[j][3];
        }
        s0 = qred_sum(s0);
        s1 = qred_sum(s1);
        lrow0 = lrow0 * al0 + s0;
        lrow1 = lrow1 * al1 + s1;
#pragma unroll
        for (int j = 0; j < 8; j++) {
            ofr[j][0] *= al0; ofr[j][1] *= al0;
            ofr[j][2] *= al1; ofr[j][3] *= al1;
        }

        // ---- O += P V (pipelined V frags, 2 buffers) ----
#pragma unroll
        for (int kc = 0; kc < 4; kc++) {
            uint32_t ph[4], pl[4];
            packsplit(cfr[2 * kc][0],     cfr[2 * kc][1],     ph[0], pl[0]);
            packsplit(cfr[2 * kc][2],     cfr[2 * kc][3],     ph[1], pl[1]);
            packsplit(cfr[2 * kc + 1][0], cfr[2 * kc + 1][1], ph[2], pl[2]);
            packsplit(cfr[2 * kc + 1][2], cfr[2 * kc + 1][3], ph[3], pl[3]);
            uint32_t vb[2][4];
            auto LV = [&](int nc, int bp) {
                const uint32_t off = swz((uint32_t)((kc * 16 + lrow16) * 128 + nc * 32 + lhi));
                ldsm4t(vb[bp], kvb + 8192 + off);
            };
            auto MV = [&](int nc, int bp) {
                mma2(ofr[2 * nc],     ph, vb[bp][0], vb[bp][1]);
                mma2(ofr[2 * nc],     pl, vb[bp][0], vb[bp][1]);
                mma2(ofr[2 * nc + 1], ph, vb[bp][2], vb[bp][3]);
                mma2(ofr[2 * nc + 1], pl, vb[bp][2], vb[bp][3]);
            };
            LV(0, 0); LV(1, 1);
            MV(0, 0); LV(2, 0);
            MV(1, 1); LV(3, 1);
            MV(2, 0);
            MV(3, 1);
        }
    }

    // ---- epilogue: write hi/lo fp16 into [B,T,C] for proj GEMM ----
    const float inv0 = 1.f / lrow0, inv1 = 1.f / lrow1;
    const int b = bh >> 4, h = bh & 15;
    const int t0 = qb * 128 + wid * 16 + g;
#pragma unroll
    for (int j = 0; j < 8; j++) {
        const int d = j * 8 + t2;
        const size_t i0 = ((size_t)(b * T_ + t0)) * C_ + h * 64 + d;
        const size_t i1 = i0 + (size_t)8 * C_;
        uint32_t hi, lo;
        packsplit(ofr[j][0] * inv0, ofr[j][1] * inv0, hi, lo);
        *(uint32_t*)&g_ah[i0] = hi;
        *(uint32_t*)&g_al[i0] = lo;
        packsplit(ofr[j][2] * inv1, ofr[j][3] * inv1, hi, lo);
        *(uint32_t*)&g_ah[i1] = hi;
        *(uint32_t*)&g_al[i1] = lo;
    }
}

// ---------------------------------------------------------------------------
// Launch. Inputs: x, mask, W_attn, b_attn, W_proj, b_proj.
// Output: [out (B,T,C) | k (B,H,T,D) | v (B,H,T,D)] fp32.
// ---------------------------------------------------------------------------
extern "C" void kernel_launch(void* const* d_in, const int* in_sizes, int n_in,
                              void* d_out, int out_size)
{
    (void)in_sizes; (void)n_in; (void)out_size;
    const float* x      = (const float*)d_in[0];
    const float* W_attn = (const float*)d_in[2];
    const float* b_attn = (const float*)d_in[3];
    const float* W_proj = (const float*)d_in[4];
    const float* b_proj = (const float*)d_in[5];

    float* out  = (float*)d_out;
    float* kout = out + (size_t)B_ * H_ * T_ * D_;
    float* vout = kout + (size_t)B_ * H_ * T_ * D_;

    cudaFuncSetAttribute(mma_gemm<0>, cudaFuncAttributeMaxDynamicSharedMemorySize,
                         SMEM_GEMM_BYTES);
    cudaFuncSetAttribute(mma_gemm<1>, cudaFuncAttributeMaxDynamicSharedMemorySize,
                         SMEM_GEMM_BYTES);
    cudaFuncSetAttribute(attn_mma, cudaFuncAttributeMaxDynamicSharedMemorySize,
                         AT_SMEM);

    // 1) conversions
    split_x<<<1024, 256>>>(x);
    tsplit_kernel<0><<<dim3(96, 32), dim3(32, 8)>>>(W_attn);
    tsplit_kernel<1><<<dim3(32, 32), dim3(32, 8)>>>(W_proj);

    // 2) QKV GEMM + bias + scatter (N tile 64 -> grid x = 48)
    mma_gemm<0><<<dim3(48, 64), 256, SMEM_GEMM_BYTES>>>(b_attn, nullptr, kout, vout);

    // 3) causal flash attention (tensor cores) -> g_ah/g_al
    attn_mma<<<dim3(16, 64), 256, AT_SMEM>>>();

    // 4) proj GEMM (grid x = 16)
    mma_gemm<1><<<dim3(16, 64), 256, SMEM_GEMM_BYTES>>>(b_proj, out, nullptr, nullptr);
}

// round 8
// speedup vs baseline: 4.7538x; 1.0018x over previous
#include <cuda_runtime.h>
#include <cuda_fp16.h>
#include <cstdint>

// Problem constants
#define B_ 4
#define T_ 2048
#define C_ 1024
#define H_ 16
#define D_ 64
#define BT_ (B_ * T_)            // 8192
#define KDIM 1024

#define QSCALE 0.18033688011112042f   // 0.125 * log2(e)

// ---------------------------------------------------------------------------
// Scratch (device globals — no allocation allowed). All splits fp16 hi/lo.
// ---------------------------------------------------------------------------
__device__ __half g_xh[(size_t)BT_ * KDIM];    // x hi/lo
__device__ __half g_xl[(size_t)BT_ * KDIM];
__device__ __half g_wh[(size_t)3 * C_ * KDIM]; // W_attn^T hi [3072][1024]
__device__ __half g_ph[(size_t)C_ * KDIM];     // W_proj^T hi [1024][1024]
__device__ __half g_ah[(size_t)BT_ * KDIM];    // attn-out hi/lo [B,T,C]
__device__ __half g_al[(size_t)BT_ * KDIM];
// Q hi/lo, K hi, V hi in [B,H,T,D]; q pre-scaled by QSCALE
__device__ __half g_qh[(size_t)BT_ * C_];
__device__ __half g_ql[(size_t)BT_ * C_];
__device__ __half g_kh[(size_t)BT_ * C_];
__device__ __half g_vh[(size_t)BT_ * C_];

// ---------------------------------------------------------------------------
// helpers (sm_80-era PTX — legal at compute_103 base)
// ---------------------------------------------------------------------------
__device__ __forceinline__ uint32_t s2u(const void* p) {
    uint32_t a;
    asm("{ .reg .u64 t; cvta.to.shared.u64 t, %1; cvt.u32.u64 %0, t; }" : "=r"(a) : "l"(p));
    return a;
}
__device__ __forceinline__ uint32_t swz(uint32_t off) {   // SW128
    return off ^ ((off >> 3) & 0x70);
}
__device__ __forceinline__ void cp_async16(uint32_t dst, const void* src) {
    asm volatile("cp.async.cg.shared.global [%0], [%1], 16;" :: "r"(dst), "l"(src) : "memory");
}
__device__ __forceinline__ void ldsm4(uint32_t* r, uint32_t addr) {
    asm volatile("ldmatrix.sync.aligned.m8n8.x4.shared.b16 {%0,%1,%2,%3}, [%4];"
                 : "=r"(r[0]), "=r"(r[1]), "=r"(r[2]), "=r"(r[3]) : "r"(addr));
}
__device__ __forceinline__ void ldsm4t(uint32_t* r, uint32_t addr) {
    asm volatile("ldmatrix.sync.aligned.m8n8.x4.trans.shared.b16 {%0,%1,%2,%3}, [%4];"
                 : "=r"(r[0]), "=r"(r[1]), "=r"(r[2]), "=r"(r[3]) : "r"(addr));
}
__device__ __forceinline__ void mma2(float* c, const uint32_t* a, uint32_t b0, uint32_t b1) {
    asm volatile(
        "mma.sync.aligned.m16n8k16.row.col.f32.f16.f16.f32 "
        "{%0,%1,%2,%3}, {%4,%5,%6,%7}, {%8,%9}, {%0,%1,%2,%3};"
        : "+f"(c[0]), "+f"(c[1]), "+f"(c[2]), "+f"(c[3])
        : "r"(a[0]), "r"(a[1]), "r"(a[2]), "r"(a[3]), "r"(b0), "r"(b1));
}
__device__ __forceinline__ uint32_t packh2(float x, float y) {
    __half2 t; t.x = __float2half(x); t.y = __float2half(y);
    return *(uint32_t*)&t;
}
__device__ __forceinline__ void packsplit(float x, float y, uint32_t& hi, uint32_t& lo) {
    __half2 h, l;
    h.x = __float2half(x); h.y = __float2half(y);
    l.x = __float2half(x - __half2float(h.x));
    l.y = __float2half(y - __half2float(h.y));
    hi = *(uint32_t*)&h; lo = *(uint32_t*)&l;
}
__device__ __forceinline__ float qred_max(float v) {
    v = fmaxf(v, __shfl_xor_sync(~0u, v, 1));
    return fmaxf(v, __shfl_xor_sync(~0u, v, 2));
}
__device__ __forceinline__ float qred_sum(float v) {
    v += __shfl_xor_sync(~0u, v, 1);
    return v + __shfl_xor_sync(~0u, v, 2);
}

// ---------------------------------------------------------------------------
// Conversion kernels
// ---------------------------------------------------------------------------
__global__ void split_x(const float* __restrict__ s)
{
    const size_t n4 = (size_t)BT_ * KDIM / 4;
    for (size_t i = (size_t)blockIdx.x * blockDim.x + threadIdx.x; i < n4;
         i += (size_t)gridDim.x * blockDim.x) {
        float4 v = ((const float4*)s)[i];
        uint32_t h0, l0, h1, l1;
        packsplit(v.x, v.y, h0, l0);
        packsplit(v.z, v.w, h1, l1);
        ((uint32_t*)g_xh)[2 * i] = h0; ((uint32_t*)g_xh)[2 * i + 1] = h1;
        ((uint32_t*)g_xl)[2 * i] = l0; ((uint32_t*)g_xl)[2 * i + 1] = l1;
    }
}

// fp32 W [K=1024, NC] row-major -> transposed fp16 hi [NC, 1024]
template <int W>
__global__ void tsplit_kernel(const float* __restrict__ src)
{
    constexpr int NC = (W == 0) ? 3 * C_ : C_;
    __half* dh = (W == 0) ? g_wh : g_ph;
    __shared__ float tile[32][33];
    const int x = blockIdx.x * 32 + threadIdx.x;
    const int y0 = blockIdx.y * 32;
#pragma unroll
    for (int j = 0; j < 32; j += 8)
        tile[threadIdx.y + j][threadIdx.x] = src[(size_t)(y0 + threadIdx.y + j) * NC + x];
    __syncthreads();
    const int ox = y0 + threadIdx.x;
    const int oyb = blockIdx.x * 32;
#pragma unroll
    for (int j = 0; j < 32; j += 8)
        dh[(size_t)(oyb + threadIdx.y + j) * KDIM + ox] =
            __float2half(tile[threadIdx.x][threadIdx.y + j]);
}

// ---------------------------------------------------------------------------
// fp16x2 GEMM via mma.sync: D = A x B^T, A split hi/lo, B hi only.
// CTA tile 128x128, warp tile 32x64 (8 warps = 4M x 2N), K_chunk=64,
// 2-stage cp.async, 2 CTAs/SM. Stage = [Ah 16K][Al 16K][Bh 16K] = 48KB.
// Warp tile 32x64 minimizes smem-crossbar traffic (LDSM dup: A x2, B x4).
// ---------------------------------------------------------------------------
#define SM_STAGE 49152
#define SMEM_GEMM_BYTES 98304    // 2 stages

template <int MODE>
__global__ __launch_bounds__(256, 2)
void mma_gemm(const float* __restrict__ bias,
              float* __restrict__ o0, float* __restrict__ o1, float* __restrict__ o2)
{
    extern __shared__ __align__(1024) char smem[];
    const uint32_t sm = s2u(smem);
    const int tid = threadIdx.x;
    const int wid = tid >> 5;
    const int lid = tid & 31;
    const int n0 = blockIdx.x * 128;
    const int m0 = blockIdx.y * 128;

    const __half* Ahp = (MODE == 0) ? g_xh : g_ah;
    const __half* Alp = (MODE == 0) ? g_xl : g_al;
    const __half* Bhp = (MODE == 0) ? g_wh : g_ph;

    // copy plan: 3072 x 16B per stage, 12 per thread
    auto issue_loads = [&](int c, int s) {
        const uint32_t sb = sm + (uint32_t)s * SM_STAGE;
#pragma unroll
        for (int r = 0; r < 12; r++) {
            const int id = tid + r * 256;
            const int row = (id >> 3) & 127;
            const int c16 = id & 7;
            const uint32_t off = swz((uint32_t)(row * 128 + c16 * 16));
            if (id < 1024)
                cp_async16(sb + off, Ahp + (size_t)(m0 + row) * KDIM + c * 64 + c16 * 8);
            else if (id < 2048)
                cp_async16(sb + 16384 + off, Alp + (size_t)(m0 + row) * KDIM + c * 64 + c16 * 8);
            else
                cp_async16(sb + 32768 + off, Bhp + (size_t)(n0 + row) * KDIM + c * 64 + c16 * 8);
        }
        asm volatile("cp.async.commit_group;" ::: "memory");
    };

    const int wm = (wid & 3) * 32;       // warp M origin (4 rows of warps)
    const int wn = (wid >> 2) * 64;      // warp N origin (2 cols of warps)
    const int g = lid >> 2;
    const int tig = lid & 3;
    const int aRow = lid & 15;
    const int aKb = (lid >> 4) * 16;
    const int bRow = ((lid >> 4) & 1) * 8 + (lid & 7);
    const int bKb = ((lid >> 3) & 1) * 16;

    float Cr[2][8][4];                   // [mi][n8 slice][quad]
#pragma unroll
    for (int mi = 0; mi < 2; mi++)
#pragma unroll
        for (int j = 0; j < 8; j++)
#pragma unroll
            for (int qi = 0; qi < 4; qi++) Cr[mi][j][qi] = 0.f;

    issue_loads(0, 0);
    issue_loads(1, 1);

    for (int c = 0; c < 16; c++) {
        const int s = c & 1;
        if (c < 15) asm volatile("cp.async.wait_group 1;" ::: "memory");
        else        asm volatile("cp.async.wait_group 0;" ::: "memory");
        __syncthreads();

        const uint32_t sb = sm + (uint32_t)s * SM_STAGE;
        const uint32_t tAh = sb, tAl = sb + 16384, tBh = sb + 32768;

#pragma unroll
        for (int ks = 0; ks < 4; ks++) {
            const int kb = ks * 32;
            uint32_t ah[2][4], al[2][4], bh[4][4];
#pragma unroll
            for (int mi = 0; mi < 2; mi++) {
                const uint32_t off = swz((uint32_t)((wm + mi * 16 + aRow) * 128 + kb + aKb));
                ldsm4(ah[mi], tAh + off);
                ldsm4(al[mi], tAl + off);
            }
#pragma unroll
            for (int jp = 0; jp < 4; jp++) {
                const uint32_t off = swz((uint32_t)((wn + jp * 16 + bRow) * 128 + kb + bKb));
                ldsm4(bh[jp], tBh + off);
            }
#pragma unroll
            for (int mi = 0; mi < 2; mi++)
#pragma unroll
                for (int j = 0; j < 8; j++) {
                    const int jp = j >> 1, o = (j & 1) * 2;
                    mma2(Cr[mi][j], ah[mi], bh[jp][o], bh[jp][o + 1]);
                    mma2(Cr[mi][j], al[mi], bh[jp][o], bh[jp][o + 1]);
                }
        }
        __syncthreads();              // all smem reads of stage s done
        if (c + 2 < 16) issue_loads(c + 2, s);
    }

    // ---- epilogue ----
#pragma unroll
    for (int mi = 0; mi < 2; mi++)
#pragma unroll
        for (int j = 0; j < 8; j++) {
            const int col = n0 + wn + (j >> 1) * 16 + (j & 1) * 8 + tig * 2;
            const float2 bb = *(const float2*)(bias + col);
#pragma unroll
            for (int half = 0; half < 2; half++) {
                const int row = m0 + wm + mi * 16 + g + half * 8;
                float2 v;
                v.x = Cr[mi][j][half * 2 + 0] + bb.x;
                v.y = Cr[mi][j][half * 2 + 1] + bb.y;
                if (MODE == 0) {
                    const int seg = col >> 10;
                    const int c0 = col & 1023;
                    const int h = c0 >> 6;
                    const int dd = c0 & 63;
                    const int b = row >> 11;
                    const int t = row & (T_ - 1);
                    const size_t idx = ((size_t)(b * H_ + h) * T_ + t) * D_ + dd;
                    if (seg == 0) {
                        uint32_t hi, lo;
                        packsplit(v.x * QSCALE, v.y * QSCALE, hi, lo);
                        *(uint32_t*)&g_qh[idx] = hi;
                        *(uint32_t*)&g_ql[idx] = lo;
                    } else if (seg == 1) {
                        *(float2*)&o1[idx] = v;
                        *(uint32_t*)&g_kh[idx] = packh2(v.x, v.y);
                    } else {
                        *(float2*)&o2[idx] = v;
                        *(uint32_t*)&g_vh[idx] = packh2(v.x, v.y);
                    }
                } else {
                    *(float2*)&o0[(size_t)row * C_ + col] = v;
                }
            }
        }
}

// ---------------------------------------------------------------------------
// Flash attention via mma.sync fp16x2; 3-stage KV (single sync per tile),
// 2 CTAs/SM, pipelined K/V fragment loads. (unchanged from R7)
// ---------------------------------------------------------------------------
#define AT_SMEM 81920            // Q 32K + 3 stages x 16K

__global__ __launch_bounds__(256, 2)
void attn_mma()
{
    extern __shared__ __align__(1024) char smem[];
    const uint32_t sm = s2u(smem);
    const int tid = threadIdx.x;
    const int wid = tid >> 5;
    const int lid = tid & 31;
    const int qb = 15 - blockIdx.x;          // heavy CTAs first
    const int bh = blockIdx.y;
    const size_t base_qkv = (size_t)bh * T_ * D_;
    const int nt = 2 * qb + 2;

#pragma unroll
    for (int r = 0; r < 8; r++) {
        const int id = tid + r * 256;
        const int bsel = id >> 10;
        const int row = (id >> 3) & 127;
        const int c16 = id & 7;
        const uint32_t dst = sm + bsel * 16384 + swz((uint32_t)(row * 128 + c16 * 16));
        const __half* src = (bsel ? g_ql : g_qh) + base_qkv
                            + (size_t)(qb * 128 + row) * D_ + c16 * 8;
        cp_async16(dst, src);
    }
    auto issue_kv = [&](int kt, int s) {
        const uint32_t sb = sm + 32768 + (uint32_t)s * 16384;
#pragma unroll
        for (int r = 0; r < 4; r++) {
            const int id = tid + r * 256;
            const int bsel = id >> 9;        // 0 Kh 1 Vh
            const int row = (id >> 3) & 63;
            const int c16 = id & 7;
            const uint32_t dst = sb + bsel * 8192 + swz((uint32_t)(row * 128 + c16 * 16));
            const __half* src = (bsel ? g_vh : g_kh) + base_qkv
                                + (size_t)(kt * 64 + row) * D_ + c16 * 8;
            cp_async16(dst, src);
        }
        asm volatile("cp.async.commit_group;" ::: "memory");
    };
    issue_kv(0, 0);
    issue_kv(1, 1);

    const int g = lid >> 2;
    const int t2 = (lid & 3) * 2;
    const int lrow16 = lid & 15;
    const int lhi = (lid >> 4) * 16;

    uint32_t qh[4][4], ql[4][4];
    float cfr[8][4], ofr[8][4];
    float mrow0 = -1e30f, mrow1 = -1e30f, lrow0 = 0.f, lrow1 = 0.f;
#pragma unroll
    for (int j = 0; j < 8; j++)
#pragma unroll
        for (int qi = 0; qi < 4; qi++) ofr[j][qi] = 0.f;

    for (int kb = 0; kb < nt; kb++) {
        const int s = kb % 3;
        if (kb + 1 < nt) asm volatile("cp.async.wait_group 1;" ::: "memory");
        else             asm volatile("cp.async.wait_group 0;" ::: "memory");
        __syncthreads();
        if (kb + 2 < nt) issue_kv(kb + 2, (kb + 2) % 3);
        if (kb == 0) {
#pragma unroll
            for (int kc = 0; kc < 4; kc++) {
                const uint32_t off = swz((uint32_t)((wid * 16 + lrow16) * 128 + kc * 32 + lhi));
                ldsm4(qh[kc], sm + off);
                ldsm4(ql[kc], sm + 16384 + off);
            }
        }
        const uint32_t kvb = sm + 32768 + (uint32_t)s * 16384;

        // ---- S = Q K^T (pipelined K frags, 2 buffers) ----
#pragma unroll
        for (int j = 0; j < 8; j++)
#pragma unroll
            for (int qi = 0; qi < 4; qi++) cfr[j][qi] = 0.f;
#pragma unroll
        for (int kc = 0; kc < 4; kc++) {
            uint32_t khb[2][4];
            auto LK = [&](int jp, int bp) {
                const uint32_t off = swz((uint32_t)((jp * 16 + lrow16) * 128 + kc * 32 + lhi));
                ldsm4(khb[bp], kvb + off);
            };
            auto MS = [&](int jp, int bp) {
                mma2(cfr[2 * jp],     qh[kc], khb[bp][0], khb[bp][2]);
                mma2(cfr[2 * jp],     ql[kc], khb[bp][0], khb[bp][2]);
                mma2(cfr[2 * jp + 1], qh[kc], khb[bp][1], khb[bp][3]);
                mma2(cfr[2 * jp + 1], ql[kc], khb[bp][1], khb[bp][3]);
            };
            LK(0, 0); LK(1, 1);
            MS(0, 0); LK(2, 0);
            MS(1, 1); LK(3, 1);
            MS(2, 0);
            MS(3, 1);
        }

        // ---- causal mask (diagonal tiles only) ----
        if (kb >= 2 * qb) {
            const int qr = qb * 128 + wid * 16 + g;
            const int kv0 = kb * 64;
#pragma unroll
            for (int j = 0; j < 8; j++) {
                const int col = kv0 + j * 8 + t2;
#pragma unroll
                for (int qi = 0; qi < 4; qi++) {
                    const int row = qr + ((qi >> 1) << 3);
                    if (col + (qi & 1) > row) cfr[j][qi] = -1e30f;
                }
            }
        }

        // ---- online softmax (log2 domain) ----
        float mx0 = -1e30f, mx1 = -1e30f;
#pragma unroll
        for (int j = 0; j < 8; j++) {
            mx0 = fmaxf(mx0, fmaxf(cfr[j][0], cfr[j][1]));
            mx1 = fmaxf(mx1, fmaxf(cfr[j][2], cfr[j][3]));
        }
        mx0 = qred_max(mx0);
        mx1 = qred_max(mx1);
        const float mn0 = fmaxf(mrow0, mx0), mn1 = fmaxf(mrow1, mx1);
        const float al0 = exp2f(mrow0 - mn0), al1 = exp2f(mrow1 - mn1);
        mrow0 = mn0; mrow1 = mn1;
        float s0 = 0.f, s1 = 0.f;
#pragma unroll
        for (int j = 0; j < 8; j++) {
            cfr[j][0] = exp2f(cfr[j][0] - mn0);
            cfr[j][1] = exp2f(cfr[j][1] - mn0);
            cfr[j][2] = exp2f(cfr[j][2] - mn1);
            cfr[j][3] = exp2f(cfr[j][3] - mn1);
            s0 += cfr[j][0] + cfr[j][1];
            s1 += cfr[j][2] + cfr[j][3];
        }
        s0 = qred_sum(s0);
        s1 = qred_sum(s1);
        lrow0 = lrow0 * al0 + s0;
        lrow1 = lrow1 * al1 + s1;
#pragma unroll
        for (int j = 0; j < 8; j++) {
            ofr[j][0] *= al0; ofr[j][1] *= al0;
            ofr[j][2] *= al1; ofr[j][3] *= al1;
        }

        // ---- O += P V (pipelined V frags, 2 buffers) ----
#pragma unroll
        for (int kc = 0; kc < 4; kc++) {
            uint32_t ph[4], pl[4];
            packsplit(cfr[2 * kc][0],     cfr[2 * kc][1],     ph[0], pl[0]);
            packsplit(cfr[2 * kc][2],     cfr[2 * kc][3],     ph[1], pl[1]);
            packsplit(cfr[2 * kc + 1][0], cfr[2 * kc + 1][1], ph[2], pl[2]);
            packsplit(cfr[2 * kc + 1][2], cfr[2 * kc + 1][3], ph[3], pl[3]);
            uint32_t vb[2][4];
            auto LV = [&](int nc, int bp) {
                const uint32_t off = swz((uint32_t)((kc * 16 + lrow16) * 128 + nc * 32 + lhi));
                ldsm4t(vb[bp], kvb + 8192 + off);
            };
            auto MV = [&](int nc, int bp) {
                mma2(ofr[2 * nc],     ph, vb[bp][0], vb[bp][1]);
                mma2(ofr[2 * nc],     pl, vb[bp][0], vb[bp][1]);
                mma2(ofr[2 * nc + 1], ph, vb[bp][2], vb[bp][3]);
                mma2(ofr[2 * nc + 1], pl, vb[bp][2], vb[bp][3]);
            };
            LV(0, 0); LV(1, 1);
            MV(0, 0); LV(2, 0);
            MV(1, 1); LV(3, 1);
            MV(2, 0);
            MV(3, 1);
        }
    }

    // ---- epilogue: write hi/lo fp16 into [B,T,C] for proj GEMM ----
    const float inv0 = 1.f / lrow0, inv1 = 1.f / lrow1;
    const int b = bh >> 4, h = bh & 15;
    const int t0 = qb * 128 + wid * 16 + g;
#pragma unroll
    for (int j = 0; j < 8; j++) {
        const int d = j * 8 + t2;
        const size_t i0 = ((size_t)(b * T_ + t0)) * C_ + h * 64 + d;
        const size_t i1 = i0 + (size_t)8 * C_;
        uint32_t hi, lo;
        packsplit(ofr[j][0] * inv0, ofr[j][1] * inv0, hi, lo);
        *(uint32_t*)&g_ah[i0] = hi;
        *(uint32_t*)&g_al[i0] = lo;
        packsplit(ofr[j][2] * inv1, ofr[j][3] * inv1, hi, lo);
        *(uint32_t*)&g_ah[i1] = hi;
        *(uint32_t*)&g_al[i1] = lo;
    }
}

// ---------------------------------------------------------------------------
// Launch. Inputs: x, mask, W_attn, b_attn, W_proj, b_proj.
// Output: [out (B,T,C) | k (B,H,T,D) | v (B,H,T,D)] fp32.
// ---------------------------------------------------------------------------
extern "C" void kernel_launch(void* const* d_in, const int* in_sizes, int n_in,
                              void* d_out, int out_size)
{
    (void)in_sizes; (void)n_in; (void)out_size;
    const float* x      = (const float*)d_in[0];
    const float* W_attn = (const float*)d_in[2];
    const float* b_attn = (const float*)d_in[3];
    const float* W_proj = (const float*)d_in[4];
    const float* b_proj = (const float*)d_in[5];

    float* out  = (float*)d_out;
    float* kout = out + (size_t)B_ * H_ * T_ * D_;
    float* vout = kout + (size_t)B_ * H_ * T_ * D_;

    cudaFuncSetAttribute(mma_gemm<0>, cudaFuncAttributeMaxDynamicSharedMemorySize,
                         SMEM_GEMM_BYTES);
    cudaFuncSetAttribute(mma_gemm<1>, cudaFuncAttributeMaxDynamicSharedMemorySize,
                         SMEM_GEMM_BYTES);
    cudaFuncSetAttribute(attn_mma, cudaFuncAttributeMaxDynamicSharedMemorySize,
                         AT_SMEM);

    // 1) conversions
    split_x<<<1024, 256>>>(x);
    tsplit_kernel<0><<<dim3(96, 32), dim3(32, 8)>>>(W_attn);
    tsplit_kernel<1><<<dim3(32, 32), dim3(32, 8)>>>(W_proj);

    // 2) QKV GEMM + bias + scatter (N tile 128 -> grid x = 24)
    mma_gemm<0><<<dim3(24, 64), 256, SMEM_GEMM_BYTES>>>(b_attn, nullptr, kout, vout);

    // 3) causal flash attention (tensor cores) -> g_ah/g_al
    attn_mma<<<dim3(16, 64), 256, AT_SMEM>>>();

    // 4) proj GEMM (grid x = 8)
    mma_gemm<1><<<dim3(8, 64), 256, SMEM_GEMM_BYTES>>>(b_proj, out, nullptr, nullptr);
}